// round 2
// baseline (speedup 1.0000x reference)
#include <cuda_runtime.h>
#include <cuda_bf16.h>
#include <math.h>

#define D_MODEL 1024
#define N_HEADS 16
#define D_KV    64
#define INNER   1024
#define D_FF    4096
#define SEQ     1024
#define BATCH   2
#define M_ROWS  (BATCH * SEQ)   // 2048
#define TAB_LEN 2047            // rel in [-1023, 1023]

// ---------------- scratch (device globals: no allocation allowed) ----------
__device__ float g_x  [M_ROWS * D_MODEL];
__device__ float g_q  [M_ROWS * INNER];
__device__ float g_k  [M_ROWS * INNER];
__device__ float g_v  [M_ROWS * INNER];
__device__ float g_ctx[M_ROWS * INNER];
__device__ float g_h  [M_ROWS * D_MODEL];
__device__ float g_y  [M_ROWS * D_MODEL];
__device__ float g_mid[M_ROWS * D_FF];
__device__ float g_bias[N_HEADS * TAB_LEN];

// ---------------- RMSNorm (T5: no mean-sub, no bias) ----------------------
__global__ void rmsnorm_kernel(const float* __restrict__ in,
                               const float* __restrict__ w,
                               float* __restrict__ out) {
    int row = blockIdx.x;
    const float4* inr = (const float4*)(in + (size_t)row * D_MODEL);
    float4 v = inr[threadIdx.x];                       // 256 thr x 4 = 1024
    float ss = v.x * v.x + v.y * v.y + v.z * v.z + v.w * v.w;
    #pragma unroll
    for (int o = 16; o; o >>= 1) ss += __shfl_xor_sync(0xFFFFFFFFu, ss, o);
    __shared__ float sred[8];
    if ((threadIdx.x & 31) == 0) sred[threadIdx.x >> 5] = ss;
    __syncthreads();
    float total = 0.f;
    #pragma unroll
    for (int i = 0; i < 8; i++) total += sred[i];
    float scale = rsqrtf(total * (1.0f / D_MODEL) + 1e-6f);
    float4 wv = ((const float4*)w)[threadIdx.x];
    float4 o4 = make_float4(v.x * scale * wv.x, v.y * scale * wv.y,
                            v.z * scale * wv.z, v.w * scale * wv.w);
    ((float4*)(out + (size_t)row * D_MODEL))[threadIdx.x] = o4;
}

// ---------------- relative position bias table -----------------------------
// tab[h][rel+1023] = rel_bias[bucket(rel)][h], rel = k - q
__global__ void bias_table_kernel(const float* __restrict__ rel_bias,
                                  float* __restrict__ tab) {
    int i = blockIdx.x * blockDim.x + threadIdx.x;
    if (i >= TAB_LEN) return;
    int rel = i - 1023;
    int rb = (rel > 0) ? 16 : 0;      // NUM_BUCKETS//2 = 16
    int rp = rel < 0 ? -rel : rel;
    int val;
    if (rp < 8) {                      // max_exact = 8
        val = rp;
    } else {
        // 8 + int(log(rp/8)/log(16) * 8), clamped to 15
        float t = logf((float)rp * 0.125f) * (8.0f / 2.772588722239781f);
        int large = 8 + (int)t;
        val = large < 15 ? large : 15;
    }
    int bucket = rb + val;
    #pragma unroll
    for (int h = 0; h < N_HEADS; h++)
        tab[h * TAB_LEN + i] = rel_bias[bucket * N_HEADS + h];
}

// ---------------- GEMM: C[M,N] = A[M,K] @ W[N,K]^T (+ epilogue) ------------
// EPI: 0 = none, 1 = relu, 2 = add residual
template <int EPI>
__global__ __launch_bounds__(256)
void gemm_nt_kernel(const float* __restrict__ A, const float* __restrict__ W,
                    const float* __restrict__ res, float* __restrict__ C,
                    int M, int N, int K) {
    __shared__ float As[16][132];
    __shared__ float Ws[16][132];
    const int m0 = blockIdx.y * 128;
    const int n0 = blockIdx.x * 128;
    const int tid = threadIdx.x;
    const int tx = tid & 15;   // 0..15 -> n sub
    const int ty = tid >> 4;   // 0..15 -> m sub

    float acc[8][8];
    #pragma unroll
    for (int i = 0; i < 8; i++)
        #pragma unroll
        for (int j = 0; j < 8; j++) acc[i][j] = 0.f;

    for (int k0 = 0; k0 < K; k0 += 16) {
        #pragma unroll
        for (int t = 0; t < 2; t++) {
            int i = tid + t * 256;          // 0..511
            int row = i >> 2;               // 0..127
            int kq  = (i & 3) * 4;          // 0,4,8,12
            float4 a = *(const float4*)(A + (size_t)(m0 + row) * K + k0 + kq);
            As[kq + 0][row] = a.x; As[kq + 1][row] = a.y;
            As[kq + 2][row] = a.z; As[kq + 3][row] = a.w;
            float4 w = *(const float4*)(W + (size_t)(n0 + row) * K + k0 + kq);
            Ws[kq + 0][row] = w.x; Ws[kq + 1][row] = w.y;
            Ws[kq + 2][row] = w.z; Ws[kq + 3][row] = w.w;
        }
        __syncthreads();
        #pragma unroll
        for (int kk = 0; kk < 16; kk++) {
            float af[8], wf[8];
            *(float4*)(af)     = *(const float4*)&As[kk][ty * 8];
            *(float4*)(af + 4) = *(const float4*)&As[kk][ty * 8 + 4];
            *(float4*)(wf)     = *(const float4*)&Ws[kk][tx * 8];
            *(float4*)(wf + 4) = *(const float4*)&Ws[kk][tx * 8 + 4];
            #pragma unroll
            for (int i = 0; i < 8; i++)
                #pragma unroll
                for (int j = 0; j < 8; j++)
                    acc[i][j] = fmaf(af[i], wf[j], acc[i][j]);
        }
        __syncthreads();
    }

    #pragma unroll
    for (int i = 0; i < 8; i++) {
        int m = m0 + ty * 8 + i;
        #pragma unroll
        for (int j = 0; j < 8; j += 4) {
            int n = n0 + tx * 8 + j;
            float4 r = make_float4(acc[i][j], acc[i][j + 1],
                                   acc[i][j + 2], acc[i][j + 3]);
            if (EPI == 1) {
                r.x = fmaxf(r.x, 0.f); r.y = fmaxf(r.y, 0.f);
                r.z = fmaxf(r.z, 0.f); r.w = fmaxf(r.w, 0.f);
            } else if (EPI == 2) {
                float4 rv = *(const float4*)(res + (size_t)m * N + n);
                r.x += rv.x; r.y += rv.y; r.z += rv.z; r.w += rv.w;
            }
            *(float4*)(C + (size_t)m * N + n) = r;
        }
    }
}

// ---------------- flash-style attention ------------------------------------
// grid: (SEQ/128, BATCH*N_HEADS), block 128. Each thread owns one q-row.
__global__ __launch_bounds__(128)
void attention_kernel(const float* __restrict__ Q, const float* __restrict__ Kt,
                      const float* __restrict__ V, const float* __restrict__ tab,
                      float* __restrict__ O) {
    const int bh = blockIdx.y;
    const int b = bh / N_HEADS, h = bh % N_HEADS;
    const int r = blockIdx.x * 128 + threadIdx.x;

    float q[64], o[64];
    const float* qrow = Q + ((size_t)(b * SEQ + r) * INNER + h * D_KV);
    #pragma unroll
    for (int d = 0; d < 64; d += 4) {
        float4 t = *(const float4*)(qrow + d);
        q[d] = t.x; q[d + 1] = t.y; q[d + 2] = t.z; q[d + 3] = t.w;
    }
    #pragma unroll
    for (int d = 0; d < 64; d++) o[d] = 0.f;
    float m = -INFINITY, l = 0.f;

    __shared__ float Ks[64][64];
    __shared__ float Vs[64][64];
    const float* btab = tab + h * TAB_LEN + (1023 - r);  // index + k -> rel+1023

    for (int k0 = 0; k0 < SEQ; k0 += 64) {
        __syncthreads();
        #pragma unroll
        for (int t = 0; t < 8; t++) {
            int i = threadIdx.x + t * 128;   // 0..1023
            int row = i >> 4, c4 = (i & 15) * 4;
            size_t g = (size_t)(b * SEQ + k0 + row) * INNER + h * D_KV + c4;
            *(float4*)&Ks[row][c4] = *(const float4*)(Kt + g);
            *(float4*)&Vs[row][c4] = *(const float4*)(V + g);
        }
        __syncthreads();

        #pragma unroll 1
        for (int jj = 0; jj < 64; jj += 16) {
            float s[16];
            #pragma unroll
            for (int j = 0; j < 16; j++) {
                float a = btab[k0 + jj + j];
                #pragma unroll
                for (int d = 0; d < 64; d++) a = fmaf(q[d], Ks[jj + j][d], a);
                s[j] = a;
            }
            float mt = m;
            #pragma unroll
            for (int j = 0; j < 16; j++) mt = fmaxf(mt, s[j]);
            float scale = __expf(m - mt);
            m = mt;
            l *= scale;
            #pragma unroll
            for (int d = 0; d < 64; d++) o[d] *= scale;
            #pragma unroll
            for (int j = 0; j < 16; j++) {
                float p = __expf(s[j] - mt);
                l += p;
                #pragma unroll
                for (int d = 0; d < 64; d++) o[d] = fmaf(p, Vs[jj + j][d], o[d]);
            }
        }
    }
    float inv = 1.f / l;
    float* orow = O + ((size_t)(b * SEQ + r) * INNER + h * D_KV);
    #pragma unroll
    for (int d = 0; d < 64; d += 4) {
        float4 t = make_float4(o[d] * inv, o[d + 1] * inv,
                               o[d + 2] * inv, o[d + 3] * inv);
        *(float4*)(orow + d) = t;
    }
}

// ---------------- launch ---------------------------------------------------
extern "C" void kernel_launch(void* const* d_in, const int* in_sizes, int n_in,
                              void* d_out, int out_size) {
    const float* hidden  = (const float*)d_in[0];
    const float* ln1_w   = (const float*)d_in[1];
    const float* wq      = (const float*)d_in[2];
    const float* wk      = (const float*)d_in[3];
    const float* wv      = (const float*)d_in[4];
    const float* wo      = (const float*)d_in[5];
    const float* relbias = (const float*)d_in[6];
    const float* ln2_w   = (const float*)d_in[7];
    const float* wi      = (const float*)d_in[8];
    const float* wo_ff   = (const float*)d_in[9];
    float* out = (float*)d_out;

    float *px, *pq, *pk, *pv, *pctx, *ph, *py, *pmid, *pbias;
    cudaGetSymbolAddress((void**)&px,   g_x);
    cudaGetSymbolAddress((void**)&pq,   g_q);
    cudaGetSymbolAddress((void**)&pk,   g_k);
    cudaGetSymbolAddress((void**)&pv,   g_v);
    cudaGetSymbolAddress((void**)&pctx, g_ctx);
    cudaGetSymbolAddress((void**)&ph,   g_h);
    cudaGetSymbolAddress((void**)&py,   g_y);
    cudaGetSymbolAddress((void**)&pmid, g_mid);
    cudaGetSymbolAddress((void**)&pbias, g_bias);

    // LN1 + bias table
    rmsnorm_kernel<<<M_ROWS, 256>>>(hidden, ln1_w, px);
    bias_table_kernel<<<(TAB_LEN + 255) / 256, 256>>>(relbias, pbias);

    // QKV projections
    dim3 g1024(D_MODEL / 128, M_ROWS / 128);
    gemm_nt_kernel<0><<<g1024, 256>>>(px, wq, nullptr, pq, M_ROWS, INNER, D_MODEL);
    gemm_nt_kernel<0><<<g1024, 256>>>(px, wk, nullptr, pk, M_ROWS, INNER, D_MODEL);
    gemm_nt_kernel<0><<<g1024, 256>>>(px, wv, nullptr, pv, M_ROWS, INNER, D_MODEL);

    // attention
    attention_kernel<<<dim3(SEQ / 128, BATCH * N_HEADS), 128>>>(pq, pk, pv, pbias, pctx);

    // out projection + residual -> h
    gemm_nt_kernel<2><<<g1024, 256>>>(pctx, wo, hidden, ph, M_ROWS, D_MODEL, INNER);

    // LN2
    rmsnorm_kernel<<<M_ROWS, 256>>>(ph, ln2_w, py);

    // FFN
    dim3 g4096(D_FF / 128, M_ROWS / 128);
    gemm_nt_kernel<1><<<g4096, 256>>>(py, wi, nullptr, pmid, M_ROWS, D_FF, D_MODEL);
    gemm_nt_kernel<2><<<g1024, 256>>>(pmid, wo_ff, ph, out, M_ROWS, D_MODEL, D_FF);
}

// round 6
// speedup vs baseline: 1.3758x; 1.3758x over previous
#include <cuda_runtime.h>
#include <cuda_bf16.h>
#include <math.h>
#include <stdint.h>

#define D_MODEL 1024
#define N_HEADS 16
#define D_KV    64
#define INNER   1024
#define QKV_N   3072
#define D_FF    4096
#define SEQ     1024
#define BATCH   2
#define M_ROWS  (BATCH * SEQ)   // 2048
#define TAB_LEN 2047            // rel in [-1023, 1023]

// ---------------- scratch (device globals: no allocation allowed) ----------
__device__ float g_x   [M_ROWS * D_MODEL];
__device__ float g_qkv [M_ROWS * QKV_N];
__device__ float g_ctx [M_ROWS * INNER];
__device__ float g_h   [M_ROWS * D_MODEL];
__device__ float g_y   [M_ROWS * D_MODEL];
__device__ float g_mid [M_ROWS * D_FF];
__device__ float g_bias[N_HEADS * TAB_LEN];
// tf32-rounded weight copies
__device__ float g_wqkv_r[QKV_N * D_MODEL];
__device__ float g_wo_r  [D_MODEL * INNER];
__device__ float g_wi_r  [D_FF * D_MODEL];
__device__ float g_woff_r[D_MODEL * D_FF];

// ---------------- helpers ----------------------------------------------------
__device__ __forceinline__ float to_tf32(float x) {
    float r;
    asm("cvt.rna.tf32.f32 %0, %1;" : "=f"(r) : "f"(x));
    return r;
}
__device__ __forceinline__ uint32_t smem_u32(const void* p) {
    uint32_t a;
    asm("{ .reg .u64 t; cvta.to.shared.u64 t, %1; cvt.u32.u64 %0, t; }"
        : "=r"(a) : "l"(p));
    return a;
}
#define CP_ASYNC16(sm, gp) \
    asm volatile("cp.async.cg.shared.global [%0], [%1], 16;" :: "r"(sm), "l"(gp))
#define CP_COMMIT() asm volatile("cp.async.commit_group;" ::: "memory")
template <int NN>
__device__ __forceinline__ void cp_wait() {
    asm volatile("cp.async.wait_group %0;" :: "n"(NN) : "memory");
}

__device__ __forceinline__ void mma_tf32(float* d, const uint32_t* a, const uint32_t* b) {
    asm volatile(
        "mma.sync.aligned.m16n8k8.row.col.f32.tf32.tf32.f32 "
        "{%0,%1,%2,%3}, {%4,%5,%6,%7}, {%8,%9}, {%0,%1,%2,%3};"
        : "+f"(d[0]), "+f"(d[1]), "+f"(d[2]), "+f"(d[3])
        : "r"(a[0]), "r"(a[1]), "r"(a[2]), "r"(a[3]), "r"(b[0]), "r"(b[1]));
}

// ---------------- weight rounding to tf32 -----------------------------------
__global__ void round_tf32_kernel(const float4* __restrict__ in,
                                  float4* __restrict__ out, int n4) {
    int i = blockIdx.x * blockDim.x + threadIdx.x;
    if (i < n4) {
        float4 v = in[i];
        v.x = to_tf32(v.x); v.y = to_tf32(v.y);
        v.z = to_tf32(v.z); v.w = to_tf32(v.w);
        out[i] = v;
    }
}

// ---------------- RMSNorm (T5), output rounded to tf32 ----------------------
__global__ void rmsnorm_kernel(const float* __restrict__ in,
                               const float* __restrict__ w,
                               float* __restrict__ out) {
    int row = blockIdx.x;
    const float4* inr = (const float4*)(in + (size_t)row * D_MODEL);
    float4 v = inr[threadIdx.x];
    float ss = v.x * v.x + v.y * v.y + v.z * v.z + v.w * v.w;
    #pragma unroll
    for (int o = 16; o; o >>= 1) ss += __shfl_xor_sync(0xFFFFFFFFu, ss, o);
    __shared__ float sred[8];
    if ((threadIdx.x & 31) == 0) sred[threadIdx.x >> 5] = ss;
    __syncthreads();
    float total = 0.f;
    #pragma unroll
    for (int i = 0; i < 8; i++) total += sred[i];
    float scale = rsqrtf(total * (1.0f / D_MODEL) + 1e-6f);
    float4 wv = ((const float4*)w)[threadIdx.x];
    float4 o4 = make_float4(to_tf32(v.x * scale * wv.x), to_tf32(v.y * scale * wv.y),
                            to_tf32(v.z * scale * wv.z), to_tf32(v.w * scale * wv.w));
    ((float4*)(out + (size_t)row * D_MODEL))[threadIdx.x] = o4;
}

// ---------------- relative position bias table ------------------------------
__global__ void bias_table_kernel(const float* __restrict__ rel_bias,
                                  float* __restrict__ tab) {
    int i = blockIdx.x * blockDim.x + threadIdx.x;
    if (i >= TAB_LEN) return;
    int rel = i - 1023;
    int rb = (rel > 0) ? 16 : 0;
    int rp = rel < 0 ? -rel : rel;
    int val;
    if (rp < 8) {
        val = rp;
    } else {
        float t = logf((float)rp * 0.125f) * (8.0f / 2.772588722239781f);
        int large = 8 + (int)t;
        val = large < 15 ? large : 15;
    }
    int bucket = rb + val;
    #pragma unroll
    for (int h = 0; h < N_HEADS; h++)
        tab[h * TAB_LEN + i] = rel_bias[bucket * N_HEADS + h];
}

// ---------------- tf32 mma.sync GEMM: C[M,N] = A[M,K] @ W[N,K]^T ------------
// EPI: 0 = none, 1 = relu + round-to-tf32, 2 = add residual
// Tiles: CTA 128x128, BK=32; 8 warps, each 64(m) x 32(n).
// smem: [row][36] floats per tile (pitch 144B): cp.async 16B stores aligned,
// mma fragment LDS conflict-free (bank = (gid*4+tig) % 32 covers all banks).
#define SPITCH 36
#define TILEF  (128 * SPITCH)          // floats per tile
#define BUFF   (2 * TILEF)             // A+B per buffer
#define GEMM_SMEM (2 * BUFF * 4)       // bytes: 73728

template <int EPI>
__global__ __launch_bounds__(256, 2)
void gemm_tf32_kernel(const float* __restrict__ A, const float* __restrict__ W,
                      const float* __restrict__ res, float* __restrict__ C,
                      int M, int N, int K) {
    extern __shared__ float sm[];
    const int tid = threadIdx.x;
    const int wid = tid >> 5, lid = tid & 31;
    const int gid = lid >> 2, tig = lid & 3;
    const int wm = wid >> 2, wn = wid & 3;        // 2 x 4 warp grid
    const int m0 = blockIdx.y * 128;
    const int n0 = blockIdx.x * 128;
    const int T = K >> 5;

    float acc[4][4][4];
    #pragma unroll
    for (int i = 0; i < 4; i++)
        #pragma unroll
        for (int j = 0; j < 4; j++)
            #pragma unroll
            for (int c = 0; c < 4; c++) acc[i][j][c] = 0.f;

    const uint32_t smb = smem_u32(sm);

    // loader: A rows -> sm[buf][0..TILEF), W rows -> sm[buf][TILEF..)
    auto load_tiles = [&](int buf, int k0) {
        uint32_t base = smb + (uint32_t)buf * (BUFF * 4);
        #pragma unroll
        for (int t = 0; t < 4; t++) {
            int c = tid + t * 256;                 // 0..1023
            int row = c >> 3;
            int cb = (c & 7) * 16;                 // byte col
            uint32_t soff = (uint32_t)row * (SPITCH * 4) + cb;
            CP_ASYNC16(base + soff,
                       A + (size_t)(m0 + row) * K + k0 + (cb >> 2));
            CP_ASYNC16(base + (uint32_t)(TILEF * 4) + soff,
                       W + (size_t)(n0 + row) * K + k0 + (cb >> 2));
        }
    };

    load_tiles(0, 0);
    CP_COMMIT();

    for (int i = 0; i < T; i++) {
        const int cur = i & 1;
        if (i + 1 < T) {
            load_tiles(cur ^ 1, (i + 1) << 5);
            CP_COMMIT();
            cp_wait<1>();
        } else {
            cp_wait<0>();
        }
        __syncthreads();

        const float* As = sm + cur * BUFF;
        const float* Bs = As + TILEF;
        #pragma unroll
        for (int ks = 0; ks < 4; ks++) {
            const int k8 = ks * 8;
            uint32_t a[4][4], b[4][2];
            #pragma unroll
            for (int mi = 0; mi < 4; mi++) {
                const float* ap = As + (wm * 64 + mi * 16 + gid) * SPITCH + k8 + tig;
                a[mi][0] = __float_as_uint(ap[0]);
                a[mi][1] = __float_as_uint(ap[8 * SPITCH]);
                a[mi][2] = __float_as_uint(ap[4]);
                a[mi][3] = __float_as_uint(ap[8 * SPITCH + 4]);
            }
            #pragma unroll
            for (int nj = 0; nj < 4; nj++) {
                const float* bp = Bs + (wn * 32 + nj * 8 + gid) * SPITCH + k8 + tig;
                b[nj][0] = __float_as_uint(bp[0]);
                b[nj][1] = __float_as_uint(bp[4]);
            }
            #pragma unroll
            for (int mi = 0; mi < 4; mi++)
                #pragma unroll
                for (int nj = 0; nj < 4; nj++)
                    mma_tf32(acc[mi][nj], a[mi], b[nj]);
        }
        __syncthreads();
    }

    // epilogue
    #pragma unroll
    for (int mi = 0; mi < 4; mi++) {
        const int mA = m0 + wm * 64 + mi * 16 + gid;
        const int mB = mA + 8;
        #pragma unroll
        for (int nj = 0; nj < 4; nj++) {
            const int col = n0 + wn * 32 + nj * 8 + tig * 2;
            float2 v0 = make_float2(acc[mi][nj][0], acc[mi][nj][1]);
            float2 v1 = make_float2(acc[mi][nj][2], acc[mi][nj][3]);
            if (EPI == 1) {
                v0.x = to_tf32(fmaxf(v0.x, 0.f)); v0.y = to_tf32(fmaxf(v0.y, 0.f));
                v1.x = to_tf32(fmaxf(v1.x, 0.f)); v1.y = to_tf32(fmaxf(v1.y, 0.f));
            } else if (EPI == 2) {
                float2 r0 = *(const float2*)(res + (size_t)mA * N + col);
                float2 r1 = *(const float2*)(res + (size_t)mB * N + col);
                v0.x += r0.x; v0.y += r0.y;
                v1.x += r1.x; v1.y += r1.y;
            }
            *(float2*)(C + (size_t)mA * N + col) = v0;
            *(float2*)(C + (size_t)mB * N + col) = v1;
        }
    }
}

// ---------------- flash-style attention (SIMT, fp32) ------------------------
// QKV packed: row pitch QKV_N, Q at +0, K at +INNER, V at +2*INNER
__global__ __launch_bounds__(128)
void attention_kernel(const float* __restrict__ QKV, const float* __restrict__ tab,
                      float* __restrict__ O) {
    const int bh = blockIdx.y;
    const int b = bh / N_HEADS, h = bh % N_HEADS;
    const int r = blockIdx.x * 128 + threadIdx.x;

    float q[64], o[64];
    const float* qrow = QKV + ((size_t)(b * SEQ + r) * QKV_N + h * D_KV);
    #pragma unroll
    for (int d = 0; d < 64; d += 4) {
        float4 t = *(const float4*)(qrow + d);
        q[d] = t.x; q[d + 1] = t.y; q[d + 2] = t.z; q[d + 3] = t.w;
    }
    #pragma unroll
    for (int d = 0; d < 64; d++) o[d] = 0.f;
    float m = -INFINITY, l = 0.f;

    __shared__ float Ks[64][64];
    __shared__ float Vs[64][64];
    const float* btab = tab + h * TAB_LEN + (1023 - r);

    for (int k0 = 0; k0 < SEQ; k0 += 64) {
        __syncthreads();
        #pragma unroll
        for (int t = 0; t < 8; t++) {
            int i = threadIdx.x + t * 128;
            int row = i >> 4, c4 = (i & 15) * 4;
            size_t g = (size_t)(b * SEQ + k0 + row) * QKV_N + h * D_KV + c4;
            *(float4*)&Ks[row][c4] = *(const float4*)(QKV + INNER + g);
            *(float4*)&Vs[row][c4] = *(const float4*)(QKV + 2 * INNER + g);
        }
        __syncthreads();

        #pragma unroll 1
        for (int jj = 0; jj < 64; jj += 16) {
            float s[16];
            #pragma unroll
            for (int j = 0; j < 16; j++) {
                float a = btab[k0 + jj + j];
                #pragma unroll
                for (int d = 0; d < 64; d++) a = fmaf(q[d], Ks[jj + j][d], a);
                s[j] = a;
            }
            float mt = m;
            #pragma unroll
            for (int j = 0; j < 16; j++) mt = fmaxf(mt, s[j]);
            float scale = __expf(m - mt);
            m = mt;
            l *= scale;
            #pragma unroll
            for (int d = 0; d < 64; d++) o[d] *= scale;
            #pragma unroll
            for (int j = 0; j < 16; j++) {
                float p = __expf(s[j] - mt);
                l += p;
                #pragma unroll
                for (int d = 0; d < 64; d++) o[d] = fmaf(p, Vs[jj + j][d], o[d]);
            }
        }
    }
    float inv = 1.f / l;
    float* orow = O + ((size_t)(b * SEQ + r) * INNER + h * D_KV);
    #pragma unroll
    for (int d = 0; d < 64; d += 4) {
        float4 t = make_float4(to_tf32(o[d] * inv), to_tf32(o[d + 1] * inv),
                               to_tf32(o[d + 2] * inv), to_tf32(o[d + 3] * inv));
        *(float4*)(orow + d) = t;
    }
}

// ---------------- launch -----------------------------------------------------
extern "C" void kernel_launch(void* const* d_in, const int* in_sizes, int n_in,
                              void* d_out, int out_size) {
    const float* hidden  = (const float*)d_in[0];
    const float* ln1_w   = (const float*)d_in[1];
    const float* wq      = (const float*)d_in[2];
    const float* wk      = (const float*)d_in[3];
    const float* wv      = (const float*)d_in[4];
    const float* wo      = (const float*)d_in[5];
    const float* relbias = (const float*)d_in[6];
    const float* ln2_w   = (const float*)d_in[7];
    const float* wi      = (const float*)d_in[8];
    const float* wo_ff   = (const float*)d_in[9];
    float* out = (float*)d_out;

    float *px, *pqkv, *pctx, *ph, *py, *pmid, *pbias;
    float *pwqkv, *pwo, *pwi, *pwoff;
    cudaGetSymbolAddress((void**)&px,    g_x);
    cudaGetSymbolAddress((void**)&pqkv,  g_qkv);
    cudaGetSymbolAddress((void**)&pctx,  g_ctx);
    cudaGetSymbolAddress((void**)&ph,    g_h);
    cudaGetSymbolAddress((void**)&py,    g_y);
    cudaGetSymbolAddress((void**)&pmid,  g_mid);
    cudaGetSymbolAddress((void**)&pbias, g_bias);
    cudaGetSymbolAddress((void**)&pwqkv, g_wqkv_r);
    cudaGetSymbolAddress((void**)&pwo,   g_wo_r);
    cudaGetSymbolAddress((void**)&pwi,   g_wi_r);
    cudaGetSymbolAddress((void**)&pwoff, g_woff_r);

    cudaFuncSetAttribute(gemm_tf32_kernel<0>, cudaFuncAttributeMaxDynamicSharedMemorySize, GEMM_SMEM);
    cudaFuncSetAttribute(gemm_tf32_kernel<1>, cudaFuncAttributeMaxDynamicSharedMemorySize, GEMM_SMEM);
    cudaFuncSetAttribute(gemm_tf32_kernel<2>, cudaFuncAttributeMaxDynamicSharedMemorySize, GEMM_SMEM);

    // round weights to tf32 (wq/wk/wv packed into one [3072 x 1024] matrix)
    const int n4_small = (INNER * D_MODEL) / 4;
    const int n4_big   = (D_FF * D_MODEL) / 4;
    round_tf32_kernel<<<n4_small / 256, 256>>>((const float4*)wq, (float4*)pwqkv, n4_small);
    round_tf32_kernel<<<n4_small / 256, 256>>>((const float4*)wk,
        (float4*)(pwqkv + (size_t)INNER * D_MODEL), n4_small);
    round_tf32_kernel<<<n4_small / 256, 256>>>((const float4*)wv,
        (float4*)(pwqkv + (size_t)2 * INNER * D_MODEL), n4_small);
    round_tf32_kernel<<<n4_small / 256, 256>>>((const float4*)wo, (float4*)pwo, n4_small);
    round_tf32_kernel<<<n4_big / 256, 256>>>((const float4*)wi, (float4*)pwi, n4_big);
    round_tf32_kernel<<<n4_big / 256, 256>>>((const float4*)wo_ff, (float4*)pwoff, n4_big);

    // LN1 + bias table
    rmsnorm_kernel<<<M_ROWS, 256>>>(hidden, ln1_w, px);
    bias_table_kernel<<<(TAB_LEN + 255) / 256, 256>>>(relbias, pbias);

    // fused QKV projection: [2048 x 1024] @ [3072 x 1024]^T
    dim3 gqkv(QKV_N / 128, M_ROWS / 128);
    gemm_tf32_kernel<0><<<gqkv, 256, GEMM_SMEM>>>(px, pwqkv, nullptr, pqkv,
                                                  M_ROWS, QKV_N, D_MODEL);

    // attention
    attention_kernel<<<dim3(SEQ / 128, BATCH * N_HEADS), 128>>>(pqkv, pbias, pctx);

    // out projection + residual -> h
    dim3 g1024(D_MODEL / 128, M_ROWS / 128);
    gemm_tf32_kernel<2><<<g1024, 256, GEMM_SMEM>>>(pctx, pwo, hidden, ph,
                                                   M_ROWS, D_MODEL, INNER);

    // LN2
    rmsnorm_kernel<<<M_ROWS, 256>>>(ph, ln2_w, py);

    // FFN
    dim3 g4096(D_FF / 128, M_ROWS / 128);
    gemm_tf32_kernel<1><<<g4096, 256, GEMM_SMEM>>>(py, pwi, nullptr, pmid,
                                                   M_ROWS, D_FF, D_MODEL);
    gemm_tf32_kernel<2><<<g1024, 256, GEMM_SMEM>>>(pmid, pwoff, ph, out,
                                                   M_ROWS, D_MODEL, D_FF);
}

// round 7
// speedup vs baseline: 2.1367x; 1.5530x over previous
#include <cuda_runtime.h>
#include <cuda_bf16.h>
#include <math.h>
#include <stdint.h>

#define D_MODEL 1024
#define N_HEADS 16
#define D_KV    64
#define INNER   1024
#define QKV_N   3072
#define D_FF    4096
#define SEQ     1024
#define BATCH   2
#define M_ROWS  (BATCH * SEQ)   // 2048
#define TAB_LEN 2047            // rel in [-1023, 1023]

// ---------------- scratch (device globals: no allocation allowed) ----------
__device__ float g_x   [M_ROWS * D_MODEL];
__device__ float g_qkv [M_ROWS * QKV_N];
__device__ float g_ctx [M_ROWS * INNER];
__device__ float g_h   [M_ROWS * D_MODEL];
__device__ float g_y   [M_ROWS * D_MODEL];
__device__ float g_mid [M_ROWS * D_FF];
__device__ float g_bias[N_HEADS * TAB_LEN];

// ---------------- helpers ----------------------------------------------------
__device__ __forceinline__ float to_tf32(float x) {
    float r;
    asm("cvt.rna.tf32.f32 %0, %1;" : "=f"(r) : "f"(x));
    return r;
}
__device__ __forceinline__ uint32_t smem_u32(const void* p) {
    uint32_t a;
    asm("{ .reg .u64 t; cvta.to.shared.u64 t, %1; cvt.u32.u64 %0, t; }"
        : "=r"(a) : "l"(p));
    return a;
}
#define CP_ASYNC16(sm, gp) \
    asm volatile("cp.async.cg.shared.global [%0], [%1], 16;" :: "r"(sm), "l"(gp))
#define CP_COMMIT() asm volatile("cp.async.commit_group;" ::: "memory")
template <int NN>
__device__ __forceinline__ void cp_wait() {
    asm volatile("cp.async.wait_group %0;" :: "n"(NN) : "memory");
}

__device__ __forceinline__ void mma_tf32(float* d, const float* a, const float* b) {
    asm volatile(
        "mma.sync.aligned.m16n8k8.row.col.f32.tf32.tf32.f32 "
        "{%0,%1,%2,%3}, {%4,%5,%6,%7}, {%8,%9}, {%0,%1,%2,%3};"
        : "+f"(d[0]), "+f"(d[1]), "+f"(d[2]), "+f"(d[3])
        : "r"(__float_as_uint(a[0])), "r"(__float_as_uint(a[1])),
          "r"(__float_as_uint(a[2])), "r"(__float_as_uint(a[3])),
          "r"(__float_as_uint(b[0])), "r"(__float_as_uint(b[1])));
}

// ---------------- RMSNorm (T5) ----------------------------------------------
__global__ void rmsnorm_kernel(const float* __restrict__ in,
                               const float* __restrict__ w,
                               float* __restrict__ out) {
    int row = blockIdx.x;
    const float4* inr = (const float4*)(in + (size_t)row * D_MODEL);
    float4 v = inr[threadIdx.x];
    float ss = v.x * v.x + v.y * v.y + v.z * v.z + v.w * v.w;
    #pragma unroll
    for (int o = 16; o; o >>= 1) ss += __shfl_xor_sync(0xFFFFFFFFu, ss, o);
    __shared__ float sred[8];
    if ((threadIdx.x & 31) == 0) sred[threadIdx.x >> 5] = ss;
    __syncthreads();
    float total = 0.f;
    #pragma unroll
    for (int i = 0; i < 8; i++) total += sred[i];
    float scale = rsqrtf(total * (1.0f / D_MODEL) + 1e-6f);
    float4 wv = ((const float4*)w)[threadIdx.x];
    float4 o4 = make_float4(v.x * scale * wv.x, v.y * scale * wv.y,
                            v.z * scale * wv.z, v.w * scale * wv.w);
    ((float4*)(out + (size_t)row * D_MODEL))[threadIdx.x] = o4;
}

// ---------------- relative position bias table ------------------------------
__global__ void bias_table_kernel(const float* __restrict__ rel_bias,
                                  float* __restrict__ tab) {
    int i = blockIdx.x * blockDim.x + threadIdx.x;
    if (i >= TAB_LEN) return;
    int rel = i - 1023;
    int rb = (rel > 0) ? 16 : 0;
    int rp = rel < 0 ? -rel : rel;
    int val;
    if (rp < 8) {
        val = rp;
    } else {
        float t = logf((float)rp * 0.125f) * (8.0f / 2.772588722239781f);
        int large = 8 + (int)t;
        val = large < 15 ? large : 15;
    }
    int bucket = rb + val;
    #pragma unroll
    for (int h = 0; h < N_HEADS; h++)
        tab[h * TAB_LEN + i] = rel_bias[bucket * N_HEADS + h];
}

// ---------------- tf32 mma.sync GEMM: C[M,N] = A[M,K] @ W[N,K]^T ------------
// EPI: 0 = none, 1 = relu, 2 = add residual.  QKV3: select among 3 weight
// matrices by blockIdx.x>>3 (fused QKV, C stride Nc=3072).
// Tiles: CTA 128x128, BK=32; 8 warps, each 64(m) x 32(n).
// smem pitch 36 floats: cp.async 16B aligned, fragment LDS conflict-free.
// Operands rounded to tf32 (cvt.rna) in-register at fragment load.
#define SPITCH 36
#define TILEF  (128 * SPITCH)          // floats per tile
#define BUFF   (2 * TILEF)             // A+B per buffer
#define GEMM_SMEM (2 * BUFF * 4)       // bytes: 73728

template <int EPI, bool QKV3>
__global__ __launch_bounds__(256, 2)
void gemm_tf32_kernel(const float* __restrict__ A,
                      const float* __restrict__ W0,
                      const float* __restrict__ W1,
                      const float* __restrict__ W2,
                      const float* __restrict__ res, float* __restrict__ C,
                      int M, int Nc, int K) {
    extern __shared__ float sm[];
    const int tid = threadIdx.x;
    const int wid = tid >> 5, lid = tid & 31;
    const int gid = lid >> 2, tig = lid & 3;
    const int wm = wid >> 2, wn = wid & 3;        // 2 x 4 warp grid
    const int m0 = blockIdx.y * 128;
    const int n0 = blockIdx.x * 128;
    const int T = K >> 5;

    const float* W;
    int nw0;  // weight row of this CTA's first column
    if (QKV3) {
        const int sel = blockIdx.x >> 3;
        W = (sel == 0) ? W0 : ((sel == 1) ? W1 : W2);
        nw0 = (blockIdx.x & 7) * 128;
    } else {
        W = W0;
        nw0 = n0;
    }

    float acc[4][4][4];
    #pragma unroll
    for (int i = 0; i < 4; i++)
        #pragma unroll
        for (int j = 0; j < 4; j++)
            #pragma unroll
            for (int c = 0; c < 4; c++) acc[i][j][c] = 0.f;

    const uint32_t smb = smem_u32(sm);

    auto load_tiles = [&](int buf, int k0) {
        uint32_t base = smb + (uint32_t)buf * (BUFF * 4);
        #pragma unroll
        for (int t = 0; t < 4; t++) {
            int c = tid + t * 256;                 // 0..1023
            int row = c >> 3;
            int cb = (c & 7) * 16;                 // byte col
            uint32_t soff = (uint32_t)row * (SPITCH * 4) + cb;
            CP_ASYNC16(base + soff,
                       A + (size_t)(m0 + row) * K + k0 + (cb >> 2));
            CP_ASYNC16(base + (uint32_t)(TILEF * 4) + soff,
                       W + (size_t)(nw0 + row) * K + k0 + (cb >> 2));
        }
    };

    load_tiles(0, 0);
    CP_COMMIT();

    for (int i = 0; i < T; i++) {
        const int cur = i & 1;
        if (i + 1 < T) {
            load_tiles(cur ^ 1, (i + 1) << 5);
            CP_COMMIT();
            cp_wait<1>();
        } else {
            cp_wait<0>();
        }
        __syncthreads();

        const float* As = sm + cur * BUFF;
        const float* Bs = As + TILEF;
        #pragma unroll
        for (int ks = 0; ks < 4; ks++) {
            const int k8 = ks * 8;
            float a[4][4], b[4][2];
            #pragma unroll
            for (int mi = 0; mi < 4; mi++) {
                const float* ap = As + (wm * 64 + mi * 16 + gid) * SPITCH + k8 + tig;
                a[mi][0] = to_tf32(ap[0]);
                a[mi][1] = to_tf32(ap[8 * SPITCH]);
                a[mi][2] = to_tf32(ap[4]);
                a[mi][3] = to_tf32(ap[8 * SPITCH + 4]);
            }
            #pragma unroll
            for (int nj = 0; nj < 4; nj++) {
                const float* bp = Bs + (wn * 32 + nj * 8 + gid) * SPITCH + k8 + tig;
                b[nj][0] = to_tf32(bp[0]);
                b[nj][1] = to_tf32(bp[4]);
            }
            #pragma unroll
            for (int mi = 0; mi < 4; mi++)
                #pragma unroll
                for (int nj = 0; nj < 4; nj++)
                    mma_tf32(acc[mi][nj], a[mi], b[nj]);
        }
        __syncthreads();
    }

    // epilogue
    #pragma unroll
    for (int mi = 0; mi < 4; mi++) {
        const int mA = m0 + wm * 64 + mi * 16 + gid;
        const int mB = mA + 8;
        #pragma unroll
        for (int nj = 0; nj < 4; nj++) {
            const int col = n0 + wn * 32 + nj * 8 + tig * 2;
            float2 v0 = make_float2(acc[mi][nj][0], acc[mi][nj][1]);
            float2 v1 = make_float2(acc[mi][nj][2], acc[mi][nj][3]);
            if (EPI == 1) {
                v0.x = fmaxf(v0.x, 0.f); v0.y = fmaxf(v0.y, 0.f);
                v1.x = fmaxf(v1.x, 0.f); v1.y = fmaxf(v1.y, 0.f);
            } else if (EPI == 2) {
                float2 r0 = *(const float2*)(res + (size_t)mA * Nc + col);
                float2 r1 = *(const float2*)(res + (size_t)mB * Nc + col);
                v0.x += r0.x; v0.y += r0.y;
                v1.x += r1.x; v1.y += r1.y;
            }
            *(float2*)(C + (size_t)mA * Nc + col) = v0;
            *(float2*)(C + (size_t)mB * Nc + col) = v1;
        }
    }
}

// ---------------- flash-style attention (SIMT, fp32) ------------------------
// QKV packed: row pitch QKV_N, Q at +0, K at +INNER, V at +2*INNER
__global__ __launch_bounds__(128)
void attention_kernel(const float* __restrict__ QKV, const float* __restrict__ tab,
                      float* __restrict__ O) {
    const int bh = blockIdx.y;
    const int b = bh / N_HEADS, h = bh % N_HEADS;
    const int r = blockIdx.x * 128 + threadIdx.x;

    float q[64], o[64];
    const float* qrow = QKV + ((size_t)(b * SEQ + r) * QKV_N + h * D_KV);
    #pragma unroll
    for (int d = 0; d < 64; d += 4) {
        float4 t = *(const float4*)(qrow + d);
        q[d] = t.x; q[d + 1] = t.y; q[d + 2] = t.z; q[d + 3] = t.w;
    }
    #pragma unroll
    for (int d = 0; d < 64; d++) o[d] = 0.f;
    float m = -INFINITY, l = 0.f;

    __shared__ float Ks[64][64];
    __shared__ float Vs[64][64];
    const float* btab = tab + h * TAB_LEN + (1023 - r);

    for (int k0 = 0; k0 < SEQ; k0 += 64) {
        __syncthreads();
        #pragma unroll
        for (int t = 0; t < 8; t++) {
            int i = threadIdx.x + t * 128;
            int row = i >> 4, c4 = (i & 15) * 4;
            size_t g = (size_t)(b * SEQ + k0 + row) * QKV_N + h * D_KV + c4;
            *(float4*)&Ks[row][c4] = *(const float4*)(QKV + INNER + g);
            *(float4*)&Vs[row][c4] = *(const float4*)(QKV + 2 * INNER + g);
        }
        __syncthreads();

        #pragma unroll 1
        for (int jj = 0; jj < 64; jj += 16) {
            float s[16];
            #pragma unroll
            for (int j = 0; j < 16; j++) {
                float a = btab[k0 + jj + j];
                #pragma unroll
                for (int d = 0; d < 64; d++) a = fmaf(q[d], Ks[jj + j][d], a);
                s[j] = a;
            }
            float mt = m;
            #pragma unroll
            for (int j = 0; j < 16; j++) mt = fmaxf(mt, s[j]);
            float scale = __expf(m - mt);
            m = mt;
            l *= scale;
            #pragma unroll
            for (int d = 0; d < 64; d++) o[d] *= scale;
            #pragma unroll
            for (int j = 0; j < 16; j++) {
                float p = __expf(s[j] - mt);
                l += p;
                #pragma unroll
                for (int d = 0; d < 64; d++) o[d] = fmaf(p, Vs[jj + j][d], o[d]);
            }
        }
    }
    float inv = 1.f / l;
    float* orow = O + ((size_t)(b * SEQ + r) * INNER + h * D_KV);
    #pragma unroll
    for (int d = 0; d < 64; d += 4) {
        float4 t = make_float4(o[d] * inv, o[d + 1] * inv,
                               o[d + 2] * inv, o[d + 3] * inv);
        *(float4*)(orow + d) = t;
    }
}

// ---------------- launch -----------------------------------------------------
extern "C" void kernel_launch(void* const* d_in, const int* in_sizes, int n_in,
                              void* d_out, int out_size) {
    const float* hidden  = (const float*)d_in[0];
    const float* ln1_w   = (const float*)d_in[1];
    const float* wq      = (const float*)d_in[2];
    const float* wk      = (const float*)d_in[3];
    const float* wv      = (const float*)d_in[4];
    const float* wo      = (const float*)d_in[5];
    const float* relbias = (const float*)d_in[6];
    const float* ln2_w   = (const float*)d_in[7];
    const float* wi      = (const float*)d_in[8];
    const float* wo_ff   = (const float*)d_in[9];
    float* out = (float*)d_out;

    float *px, *pqkv, *pctx, *ph, *py, *pmid, *pbias;
    cudaGetSymbolAddress((void**)&px,    g_x);
    cudaGetSymbolAddress((void**)&pqkv,  g_qkv);
    cudaGetSymbolAddress((void**)&pctx,  g_ctx);
    cudaGetSymbolAddress((void**)&ph,    g_h);
    cudaGetSymbolAddress((void**)&py,    g_y);
    cudaGetSymbolAddress((void**)&pmid,  g_mid);
    cudaGetSymbolAddress((void**)&pbias, g_bias);

    cudaFuncSetAttribute(gemm_tf32_kernel<0, true>,  cudaFuncAttributeMaxDynamicSharedMemorySize, GEMM_SMEM);
    cudaFuncSetAttribute(gemm_tf32_kernel<1, false>, cudaFuncAttributeMaxDynamicSharedMemorySize, GEMM_SMEM);
    cudaFuncSetAttribute(gemm_tf32_kernel<2, false>, cudaFuncAttributeMaxDynamicSharedMemorySize, GEMM_SMEM);

    // launches 0,1: bias table (run twice: aligns ncu -s 5 onto the wo GEMM)
    bias_table_kernel<<<(TAB_LEN + 255) / 256, 256>>>(relbias, pbias);
    bias_table_kernel<<<(TAB_LEN + 255) / 256, 256>>>(relbias, pbias);

    // launch 2: LN1
    rmsnorm_kernel<<<M_ROWS, 256>>>(hidden, ln1_w, px);

    // launch 3: fused QKV projection [2048x1024] @ [3x 1024x1024]^T
    dim3 gqkv(QKV_N / 128, M_ROWS / 128);
    gemm_tf32_kernel<0, true><<<gqkv, 256, GEMM_SMEM>>>(
        px, wq, wk, wv, nullptr, pqkv, M_ROWS, QKV_N, D_MODEL);

    // launch 4: attention
    attention_kernel<<<dim3(SEQ / 128, BATCH * N_HEADS), 128>>>(pqkv, pbias, pctx);

    // launch 5 (ncu target): out projection + residual -> h
    dim3 g1024(D_MODEL / 128, M_ROWS / 128);
    gemm_tf32_kernel<2, false><<<g1024, 256, GEMM_SMEM>>>(
        pctx, wo, nullptr, nullptr, hidden, ph, M_ROWS, D_MODEL, INNER);

    // launch 6: LN2
    rmsnorm_kernel<<<M_ROWS, 256>>>(ph, ln2_w, py);

    // launches 7,8: FFN
    dim3 g4096(D_FF / 128, M_ROWS / 128);
    gemm_tf32_kernel<1, false><<<g4096, 256, GEMM_SMEM>>>(
        py, wi, nullptr, nullptr, nullptr, pmid, M_ROWS, D_FF, D_MODEL);
    gemm_tf32_kernel<2, false><<<g1024, 256, GEMM_SMEM>>>(
        pmid, wo_ff, nullptr, nullptr, ph, out, M_ROWS, D_MODEL, D_FF);
}

// round 8
// speedup vs baseline: 3.4464x; 1.6130x over previous
#include <cuda_runtime.h>
#include <cuda_bf16.h>
#include <math.h>
#include <stdint.h>

#define D_MODEL 1024
#define N_HEADS 16
#define D_KV    64
#define INNER   1024
#define QKV_N   3072
#define D_FF    4096
#define SEQ     1024
#define BATCH   2
#define M_ROWS  (BATCH * SEQ)   // 2048
#define TAB_LEN 2047            // rel in [-1023, 1023]

// ---------------- scratch (device globals: no allocation allowed) ----------
__device__ float g_x   [M_ROWS * D_MODEL];
__device__ float g_qkv [M_ROWS * QKV_N];
__device__ float g_ctx [M_ROWS * INNER];
__device__ float g_h   [M_ROWS * D_MODEL];
__device__ float g_y   [M_ROWS * D_MODEL];
__device__ float g_mid [M_ROWS * D_FF];
__device__ float g_bias[N_HEADS * TAB_LEN];

// ---------------- helpers ----------------------------------------------------
__device__ __forceinline__ float to_tf32(float x) {
    float r;
    asm("cvt.rna.tf32.f32 %0, %1;" : "=f"(r) : "f"(x));
    return r;
}
__device__ __forceinline__ uint32_t smem_u32(const void* p) {
    uint32_t a;
    asm("{ .reg .u64 t; cvta.to.shared.u64 t, %1; cvt.u32.u64 %0, t; }"
        : "=r"(a) : "l"(p));
    return a;
}
#define CP_ASYNC16(sm, gp) \
    asm volatile("cp.async.cg.shared.global [%0], [%1], 16;" :: "r"(sm), "l"(gp))
#define CP_COMMIT() asm volatile("cp.async.commit_group;" ::: "memory")
template <int NN>
__device__ __forceinline__ void cp_wait() {
    asm volatile("cp.async.wait_group %0;" :: "n"(NN) : "memory");
}

__device__ __forceinline__ void mma_tf32(float* d, const float* a, const float* b) {
    asm volatile(
        "mma.sync.aligned.m16n8k8.row.col.f32.tf32.tf32.f32 "
        "{%0,%1,%2,%3}, {%4,%5,%6,%7}, {%8,%9}, {%0,%1,%2,%3};"
        : "+f"(d[0]), "+f"(d[1]), "+f"(d[2]), "+f"(d[3])
        : "r"(__float_as_uint(a[0])), "r"(__float_as_uint(a[1])),
          "r"(__float_as_uint(a[2])), "r"(__float_as_uint(a[3])),
          "r"(__float_as_uint(b[0])), "r"(__float_as_uint(b[1])));
}

// ---------------- RMSNorm (T5) ----------------------------------------------
__global__ void rmsnorm_kernel(const float* __restrict__ in,
                               const float* __restrict__ w,
                               float* __restrict__ out) {
    int row = blockIdx.x;
    const float4* inr = (const float4*)(in + (size_t)row * D_MODEL);
    float4 v = inr[threadIdx.x];
    float ss = v.x * v.x + v.y * v.y + v.z * v.z + v.w * v.w;
    #pragma unroll
    for (int o = 16; o; o >>= 1) ss += __shfl_xor_sync(0xFFFFFFFFu, ss, o);
    __shared__ float sred[8];
    if ((threadIdx.x & 31) == 0) sred[threadIdx.x >> 5] = ss;
    __syncthreads();
    float total = 0.f;
    #pragma unroll
    for (int i = 0; i < 8; i++) total += sred[i];
    float scale = rsqrtf(total * (1.0f / D_MODEL) + 1e-6f);
    float4 wv = ((const float4*)w)[threadIdx.x];
    float4 o4 = make_float4(v.x * scale * wv.x, v.y * scale * wv.y,
                            v.z * scale * wv.z, v.w * scale * wv.w);
    ((float4*)(out + (size_t)row * D_MODEL))[threadIdx.x] = o4;
}

// ---------------- relative position bias table ------------------------------
__global__ void bias_table_kernel(const float* __restrict__ rel_bias,
                                  float* __restrict__ tab) {
    int i = blockIdx.x * blockDim.x + threadIdx.x;
    if (i >= TAB_LEN) return;
    int rel = i - 1023;
    int rb = (rel > 0) ? 16 : 0;
    int rp = rel < 0 ? -rel : rel;
    int val;
    if (rp < 8) {
        val = rp;
    } else {
        float t = logf((float)rp * 0.125f) * (8.0f / 2.772588722239781f);
        int large = 8 + (int)t;
        val = large < 15 ? large : 15;
    }
    int bucket = rb + val;
    #pragma unroll
    for (int h = 0; h < N_HEADS; h++)
        tab[h * TAB_LEN + i] = rel_bias[bucket * N_HEADS + h];
}

// ---------------- tf32 mma.sync GEMM: C[M,N] = A[M,K] @ W[N,K]^T ------------
#define SPITCH 36
#define TILEF  (128 * SPITCH)
#define BUFF   (2 * TILEF)
#define GEMM_SMEM (2 * BUFF * 4)       // 73728 bytes

template <int EPI, bool QKV3>
__global__ __launch_bounds__(256, 2)
void gemm_tf32_kernel(const float* __restrict__ A,
                      const float* __restrict__ W0,
                      const float* __restrict__ W1,
                      const float* __restrict__ W2,
                      const float* __restrict__ res, float* __restrict__ C,
                      int M, int Nc, int K) {
    extern __shared__ float sm[];
    const int tid = threadIdx.x;
    const int wid = tid >> 5, lid = tid & 31;
    const int gid = lid >> 2, tig = lid & 3;
    const int wm = wid >> 2, wn = wid & 3;
    const int m0 = blockIdx.y * 128;
    const int n0 = blockIdx.x * 128;
    const int T = K >> 5;

    const float* W;
    int nw0;
    if (QKV3) {
        const int sel = blockIdx.x >> 3;
        W = (sel == 0) ? W0 : ((sel == 1) ? W1 : W2);
        nw0 = (blockIdx.x & 7) * 128;
    } else {
        W = W0;
        nw0 = n0;
    }

    float acc[4][4][4];
    #pragma unroll
    for (int i = 0; i < 4; i++)
        #pragma unroll
        for (int j = 0; j < 4; j++)
            #pragma unroll
            for (int c = 0; c < 4; c++) acc[i][j][c] = 0.f;

    const uint32_t smb = smem_u32(sm);

    auto load_tiles = [&](int buf, int k0) {
        uint32_t base = smb + (uint32_t)buf * (BUFF * 4);
        #pragma unroll
        for (int t = 0; t < 4; t++) {
            int c = tid + t * 256;
            int row = c >> 3;
            int cb = (c & 7) * 16;
            uint32_t soff = (uint32_t)row * (SPITCH * 4) + cb;
            CP_ASYNC16(base + soff,
                       A + (size_t)(m0 + row) * K + k0 + (cb >> 2));
            CP_ASYNC16(base + (uint32_t)(TILEF * 4) + soff,
                       W + (size_t)(nw0 + row) * K + k0 + (cb >> 2));
        }
    };

    load_tiles(0, 0);
    CP_COMMIT();

    for (int i = 0; i < T; i++) {
        const int cur = i & 1;
        if (i + 1 < T) {
            load_tiles(cur ^ 1, (i + 1) << 5);
            CP_COMMIT();
            cp_wait<1>();
        } else {
            cp_wait<0>();
        }
        __syncthreads();

        const float* As = sm + cur * BUFF;
        const float* Bs = As + TILEF;
        #pragma unroll
        for (int ks = 0; ks < 4; ks++) {
            const int k8 = ks * 8;
            float a[4][4], b[4][2];
            #pragma unroll
            for (int mi = 0; mi < 4; mi++) {
                const float* ap = As + (wm * 64 + mi * 16 + gid) * SPITCH + k8 + tig;
                a[mi][0] = to_tf32(ap[0]);
                a[mi][1] = to_tf32(ap[8 * SPITCH]);
                a[mi][2] = to_tf32(ap[4]);
                a[mi][3] = to_tf32(ap[8 * SPITCH + 4]);
            }
            #pragma unroll
            for (int nj = 0; nj < 4; nj++) {
                const float* bp = Bs + (wn * 32 + nj * 8 + gid) * SPITCH + k8 + tig;
                b[nj][0] = to_tf32(bp[0]);
                b[nj][1] = to_tf32(bp[4]);
            }
            #pragma unroll
            for (int mi = 0; mi < 4; mi++)
                #pragma unroll
                for (int nj = 0; nj < 4; nj++)
                    mma_tf32(acc[mi][nj], a[mi], b[nj]);
        }
        __syncthreads();
    }

    #pragma unroll
    for (int mi = 0; mi < 4; mi++) {
        const int mA = m0 + wm * 64 + mi * 16 + gid;
        const int mB = mA + 8;
        #pragma unroll
        for (int nj = 0; nj < 4; nj++) {
            const int col = n0 + wn * 32 + nj * 8 + tig * 2;
            float2 v0 = make_float2(acc[mi][nj][0], acc[mi][nj][1]);
            float2 v1 = make_float2(acc[mi][nj][2], acc[mi][nj][3]);
            if (EPI == 1) {
                v0.x = fmaxf(v0.x, 0.f); v0.y = fmaxf(v0.y, 0.f);
                v1.x = fmaxf(v1.x, 0.f); v1.y = fmaxf(v1.y, 0.f);
            } else if (EPI == 2) {
                float2 r0 = *(const float2*)(res + (size_t)mA * Nc + col);
                float2 r1 = *(const float2*)(res + (size_t)mB * Nc + col);
                v0.x += r0.x; v0.y += r0.y;
                v1.x += r1.x; v1.y += r1.y;
            }
            *(float2*)(C + (size_t)mA * Nc + col) = v0;
            *(float2*)(C + (size_t)mB * Nc + col) = v1;
        }
    }
}

// ---------------- tensor-core flash attention (tf32 mma) --------------------
// CTA: 64 q-rows for one (b,h); 4 warps, each m16 over full kv/d.
// S = Q@K^T + bias, online softmax in C-fragment layout, O += P@V.
// Ks pitch 68: B-frag LDS bank (4*gid+tig) -> conflict-free.
// Vs pitch 72 (un-transposed [kv][d]): B-frag LDS bank (8*tig+gid) -> conflict-free.
// Ps pitch 68: A-frag reload conflict-free.
#define KPITCH 68
#define VPITCH 72
#define PPITCH 68
#define ATT_SMEM ((64 * KPITCH + 64 * VPITCH + 64 * PPITCH) * 4)  // 53248 B

__global__ __launch_bounds__(128, 2)
void attention_mma_kernel(const float* __restrict__ QKV,
                          const float* __restrict__ tab,
                          float* __restrict__ O) {
    extern __shared__ float smem[];
    float* Ks = smem;
    float* Vs = smem + 64 * KPITCH;
    float* Ps = smem + 64 * KPITCH + 64 * VPITCH;

    const int bh = blockIdx.y;
    const int b = bh >> 4, h = bh & 15;
    const int q0 = blockIdx.x * 64;
    const int tid = threadIdx.x;
    const int wid = tid >> 5, lid = tid & 31;
    const int gid = lid >> 2, tig = lid & 3;

    // Q fragments (A, m16 x k64), rounded to tf32 once
    float qf[8][4];
    {
        const float* Qb = QKV + (size_t)(b * SEQ + q0 + wid * 16 + gid) * QKV_N + h * D_KV;
        #pragma unroll
        for (int k = 0; k < 8; k++) {
            qf[k][0] = to_tf32(Qb[k * 8 + tig]);
            qf[k][1] = to_tf32(Qb[8 * QKV_N + k * 8 + tig]);
            qf[k][2] = to_tf32(Qb[k * 8 + tig + 4]);
            qf[k][3] = to_tf32(Qb[8 * QKV_N + k * 8 + tig + 4]);
        }
    }

    float oacc[8][4];
    #pragma unroll
    for (int nj = 0; nj < 8; nj++)
        #pragma unroll
        for (int c = 0; c < 4; c++) oacc[nj][c] = 0.f;
    float m0 = -1e30f, m1 = -1e30f, l0 = 0.f, l1 = 0.f;

    for (int k0 = 0; k0 < SEQ; k0 += 64) {
        __syncthreads();
        // load K,V chunk, tf32-rounded at store
        #pragma unroll
        for (int t = 0; t < 8; t++) {
            int idx = tid + t * 128;           // 0..1023
            int row = idx >> 4;                // 0..63
            int c4 = (idx & 15) * 4;
            size_t gaddr = (size_t)(b * SEQ + k0 + row) * QKV_N + h * D_KV + c4;
            float4 kk = *(const float4*)(QKV + INNER + gaddr);
            kk.x = to_tf32(kk.x); kk.y = to_tf32(kk.y);
            kk.z = to_tf32(kk.z); kk.w = to_tf32(kk.w);
            *(float4*)(Ks + row * KPITCH + c4) = kk;
            float4 vv = *(const float4*)(QKV + 2 * INNER + gaddr);
            vv.x = to_tf32(vv.x); vv.y = to_tf32(vv.y);
            vv.z = to_tf32(vv.z); vv.w = to_tf32(vv.w);
            *(float4*)(Vs + row * VPITCH + c4) = vv;
        }
        __syncthreads();

        // S = Q @ K^T
        float sacc[8][4];
        #pragma unroll
        for (int nj = 0; nj < 8; nj++)
            #pragma unroll
            for (int c = 0; c < 4; c++) sacc[nj][c] = 0.f;
        #pragma unroll
        for (int k = 0; k < 8; k++) {
            #pragma unroll
            for (int nj = 0; nj < 8; nj++) {
                float bf[2];
                const float* kp = Ks + (nj * 8 + gid) * KPITCH + k * 8 + tig;
                bf[0] = kp[0];
                bf[1] = kp[4];
                mma_tf32(sacc[nj], qf[k], bf);
            }
        }

        // bias + online softmax (rows gid and gid+8)
        const float* bt = tab + h * TAB_LEN + 1023 + k0 - (q0 + wid * 16);
        float rx0 = -1e30f, rx1 = -1e30f;
        #pragma unroll
        for (int nj = 0; nj < 8; nj++) {
            int c = nj * 8 + 2 * tig;
            sacc[nj][0] += __ldg(bt + c - gid);
            sacc[nj][1] += __ldg(bt + c + 1 - gid);
            sacc[nj][2] += __ldg(bt + c - gid - 8);
            sacc[nj][3] += __ldg(bt + c + 1 - gid - 8);
            rx0 = fmaxf(rx0, fmaxf(sacc[nj][0], sacc[nj][1]));
            rx1 = fmaxf(rx1, fmaxf(sacc[nj][2], sacc[nj][3]));
        }
        rx0 = fmaxf(rx0, __shfl_xor_sync(0xFFFFFFFFu, rx0, 1));
        rx0 = fmaxf(rx0, __shfl_xor_sync(0xFFFFFFFFu, rx0, 2));
        rx1 = fmaxf(rx1, __shfl_xor_sync(0xFFFFFFFFu, rx1, 1));
        rx1 = fmaxf(rx1, __shfl_xor_sync(0xFFFFFFFFu, rx1, 2));
        float mn0 = fmaxf(m0, rx0), mn1 = fmaxf(m1, rx1);
        float sc0 = __expf(m0 - mn0), sc1 = __expf(m1 - mn1);
        m0 = mn0; m1 = mn1;

        float rs0 = 0.f, rs1 = 0.f;
        float* pw0 = Ps + (wid * 16 + gid) * PPITCH;
        float* pw1 = pw0 + 8 * PPITCH;
        #pragma unroll
        for (int nj = 0; nj < 8; nj++) {
            int c = nj * 8 + 2 * tig;
            float p0 = __expf(sacc[nj][0] - m0);
            float p1 = __expf(sacc[nj][1] - m0);
            float p2 = __expf(sacc[nj][2] - m1);
            float p3 = __expf(sacc[nj][3] - m1);
            rs0 += p0 + p1; rs1 += p2 + p3;
            *(float2*)(pw0 + c) = make_float2(to_tf32(p0), to_tf32(p1));
            *(float2*)(pw1 + c) = make_float2(to_tf32(p2), to_tf32(p3));
        }
        rs0 += __shfl_xor_sync(0xFFFFFFFFu, rs0, 1);
        rs0 += __shfl_xor_sync(0xFFFFFFFFu, rs0, 2);
        rs1 += __shfl_xor_sync(0xFFFFFFFFu, rs1, 1);
        rs1 += __shfl_xor_sync(0xFFFFFFFFu, rs1, 2);
        l0 = l0 * sc0 + rs0;
        l1 = l1 * sc1 + rs1;
        #pragma unroll
        for (int nj = 0; nj < 8; nj++) {
            oacc[nj][0] *= sc0; oacc[nj][1] *= sc0;
            oacc[nj][2] *= sc1; oacc[nj][3] *= sc1;
        }
        __syncwarp();

        // O += P @ V
        #pragma unroll
        for (int k = 0; k < 8; k++) {
            float af[4];
            const float* pp = Ps + (wid * 16 + gid) * PPITCH + k * 8 + tig;
            af[0] = pp[0];
            af[1] = pp[8 * PPITCH];
            af[2] = pp[4];
            af[3] = pp[8 * PPITCH + 4];
            #pragma unroll
            for (int nj = 0; nj < 8; nj++) {
                float bf[2];
                const float* vp = Vs + (k * 8 + tig) * VPITCH + nj * 8 + gid;
                bf[0] = vp[0];
                bf[1] = vp[4 * VPITCH];
                mma_tf32(oacc[nj], af, bf);
            }
        }
        __syncwarp();
    }

    float i0 = 1.f / l0, i1 = 1.f / l1;
    float* ob = O + (size_t)(b * SEQ + q0 + wid * 16 + gid) * INNER + h * D_KV;
    #pragma unroll
    for (int nj = 0; nj < 8; nj++) {
        int c = nj * 8 + 2 * tig;
        *(float2*)(ob + c) = make_float2(oacc[nj][0] * i0, oacc[nj][1] * i0);
        *(float2*)(ob + 8 * INNER + c) = make_float2(oacc[nj][2] * i1, oacc[nj][3] * i1);
    }
}

// ---------------- launch -----------------------------------------------------
extern "C" void kernel_launch(void* const* d_in, const int* in_sizes, int n_in,
                              void* d_out, int out_size) {
    const float* hidden  = (const float*)d_in[0];
    const float* ln1_w   = (const float*)d_in[1];
    const float* wq      = (const float*)d_in[2];
    const float* wk      = (const float*)d_in[3];
    const float* wv      = (const float*)d_in[4];
    const float* wo      = (const float*)d_in[5];
    const float* relbias = (const float*)d_in[6];
    const float* ln2_w   = (const float*)d_in[7];
    const float* wi      = (const float*)d_in[8];
    const float* wo_ff   = (const float*)d_in[9];
    float* out = (float*)d_out;

    float *px, *pqkv, *pctx, *ph, *py, *pmid, *pbias;
    cudaGetSymbolAddress((void**)&px,    g_x);
    cudaGetSymbolAddress((void**)&pqkv,  g_qkv);
    cudaGetSymbolAddress((void**)&pctx,  g_ctx);
    cudaGetSymbolAddress((void**)&ph,    g_h);
    cudaGetSymbolAddress((void**)&py,    g_y);
    cudaGetSymbolAddress((void**)&pmid,  g_mid);
    cudaGetSymbolAddress((void**)&pbias, g_bias);

    cudaFuncSetAttribute(gemm_tf32_kernel<0, true>,  cudaFuncAttributeMaxDynamicSharedMemorySize, GEMM_SMEM);
    cudaFuncSetAttribute(gemm_tf32_kernel<1, false>, cudaFuncAttributeMaxDynamicSharedMemorySize, GEMM_SMEM);
    cudaFuncSetAttribute(gemm_tf32_kernel<2, false>, cudaFuncAttributeMaxDynamicSharedMemorySize, GEMM_SMEM);
    cudaFuncSetAttribute(attention_mma_kernel, cudaFuncAttributeMaxDynamicSharedMemorySize, ATT_SMEM);

    bias_table_kernel<<<(TAB_LEN + 255) / 256, 256>>>(relbias, pbias);
    rmsnorm_kernel<<<M_ROWS, 256>>>(hidden, ln1_w, px);

    // fused QKV projection [2048x1024] @ [3x 1024x1024]^T
    dim3 gqkv(QKV_N / 128, M_ROWS / 128);
    gemm_tf32_kernel<0, true><<<gqkv, 256, GEMM_SMEM>>>(
        px, wq, wk, wv, nullptr, pqkv, M_ROWS, QKV_N, D_MODEL);

    // tensor-core attention
    attention_mma_kernel<<<dim3(SEQ / 64, BATCH * N_HEADS), 128, ATT_SMEM>>>(
        pqkv, pbias, pctx);

    // out projection + residual -> h
    dim3 g1024(D_MODEL / 128, M_ROWS / 128);
    gemm_tf32_kernel<2, false><<<g1024, 256, GEMM_SMEM>>>(
        pctx, wo, nullptr, nullptr, hidden, ph, M_ROWS, D_MODEL, INNER);

    rmsnorm_kernel<<<M_ROWS, 256>>>(ph, ln2_w, py);

    // FFN
    dim3 g4096(D_FF / 128, M_ROWS / 128);
    gemm_tf32_kernel<1, false><<<g4096, 256, GEMM_SMEM>>>(
        py, wi, nullptr, nullptr, nullptr, pmid, M_ROWS, D_FF, D_MODEL);
    gemm_tf32_kernel<2, false><<<g1024, 256, GEMM_SMEM>>>(
        pmid, wo_ff, nullptr, nullptr, ph, out, M_ROWS, D_MODEL, D_FF);
}

// round 9
// speedup vs baseline: 3.4865x; 1.0116x over previous
#include <cuda_runtime.h>
#include <cuda_bf16.h>
#include <math.h>
#include <stdint.h>

#define D_MODEL 1024
#define N_HEADS 16
#define D_KV    64
#define INNER   1024
#define QKV_N   3072
#define D_FF    4096
#define SEQ     1024
#define BATCH   2
#define M_ROWS  (BATCH * SEQ)   // 2048
#define TAB_LEN 2047            // rel in [-1023, 1023]

// ---------------- scratch (device globals: no allocation allowed) ----------
__device__ float g_x   [M_ROWS * D_MODEL];
__device__ float g_qkv [M_ROWS * QKV_N];
__device__ float g_ctx [M_ROWS * INNER];
__device__ float g_h   [M_ROWS * D_MODEL];
__device__ float g_y   [M_ROWS * D_MODEL];
__device__ float g_mid [M_ROWS * D_FF];
__device__ float g_bias[N_HEADS * TAB_LEN];
// tf32-rounded weights (wq/wk/wv packed)
__device__ float g_wqkv_r[QKV_N * D_MODEL];
__device__ float g_wo_r  [D_MODEL * INNER];
__device__ float g_wi_r  [D_FF * D_MODEL];
__device__ float g_woff_r[D_MODEL * D_FF];

// ---------------- helpers ----------------------------------------------------
__device__ __forceinline__ float to_tf32(float x) {
    float r;
    asm("cvt.rna.tf32.f32 %0, %1;" : "=f"(r) : "f"(x));
    return r;
}
__device__ __forceinline__ uint32_t smem_u32(const void* p) {
    uint32_t a;
    asm("{ .reg .u64 t; cvta.to.shared.u64 t, %1; cvt.u32.u64 %0, t; }"
        : "=r"(a) : "l"(p));
    return a;
}
#define CP_ASYNC16(sm, gp) \
    asm volatile("cp.async.cg.shared.global [%0], [%1], 16;" :: "r"(sm), "l"(gp))
#define CP_COMMIT() asm volatile("cp.async.commit_group;" ::: "memory")
template <int NN>
__device__ __forceinline__ void cp_wait() {
    asm volatile("cp.async.wait_group %0;" :: "n"(NN) : "memory");
}

__device__ __forceinline__ void mma_tf32(float* d, const float* a, const float* b) {
    asm volatile(
        "mma.sync.aligned.m16n8k8.row.col.f32.tf32.tf32.f32 "
        "{%0,%1,%2,%3}, {%4,%5,%6,%7}, {%8,%9}, {%0,%1,%2,%3};"
        : "+f"(d[0]), "+f"(d[1]), "+f"(d[2]), "+f"(d[3])
        : "r"(__float_as_uint(a[0])), "r"(__float_as_uint(a[1])),
          "r"(__float_as_uint(a[2])), "r"(__float_as_uint(a[3])),
          "r"(__float_as_uint(b[0])), "r"(__float_as_uint(b[1])));
}

// ---------------- weight rounding to tf32 (once) ----------------------------
__global__ void round_tf32_kernel(const float4* __restrict__ in,
                                  float4* __restrict__ out, int n4) {
    int i = blockIdx.x * blockDim.x + threadIdx.x;
    if (i < n4) {
        float4 v = in[i];
        v.x = to_tf32(v.x); v.y = to_tf32(v.y);
        v.z = to_tf32(v.z); v.w = to_tf32(v.w);
        out[i] = v;
    }
}

// ---------------- RMSNorm (T5), output rounded to tf32 ----------------------
__global__ void rmsnorm_kernel(const float* __restrict__ in,
                               const float* __restrict__ w,
                               float* __restrict__ out) {
    int row = blockIdx.x;
    const float4* inr = (const float4*)(in + (size_t)row * D_MODEL);
    float4 v = inr[threadIdx.x];
    float ss = v.x * v.x + v.y * v.y + v.z * v.z + v.w * v.w;
    #pragma unroll
    for (int o = 16; o; o >>= 1) ss += __shfl_xor_sync(0xFFFFFFFFu, ss, o);
    __shared__ float sred[8];
    if ((threadIdx.x & 31) == 0) sred[threadIdx.x >> 5] = ss;
    __syncthreads();
    float total = 0.f;
    #pragma unroll
    for (int i = 0; i < 8; i++) total += sred[i];
    float scale = rsqrtf(total * (1.0f / D_MODEL) + 1e-6f);
    float4 wv = ((const float4*)w)[threadIdx.x];
    float4 o4 = make_float4(to_tf32(v.x * scale * wv.x), to_tf32(v.y * scale * wv.y),
                            to_tf32(v.z * scale * wv.z), to_tf32(v.w * scale * wv.w));
    ((float4*)(out + (size_t)row * D_MODEL))[threadIdx.x] = o4;
}

// ---------------- relative position bias table ------------------------------
__global__ void bias_table_kernel(const float* __restrict__ rel_bias,
                                  float* __restrict__ tab) {
    int i = blockIdx.x * blockDim.x + threadIdx.x;
    if (i >= TAB_LEN) return;
    int rel = i - 1023;
    int rb = (rel > 0) ? 16 : 0;
    int rp = rel < 0 ? -rel : rel;
    int val;
    if (rp < 8) {
        val = rp;
    } else {
        float t = logf((float)rp * 0.125f) * (8.0f / 2.772588722239781f);
        int large = 8 + (int)t;
        val = large < 15 ? large : 15;
    }
    int bucket = rb + val;
    #pragma unroll
    for (int h = 0; h < N_HEADS; h++)
        tab[h * TAB_LEN + i] = rel_bias[bucket * N_HEADS + h];
}

// ---------------- tf32 mma.sync GEMM: C[M,N] = A[M,K] @ W[N,K]^T ------------
// Inputs already tf32-rounded -> no cvt in inner loop.
// EPI: 0 = plain store, 1 = relu + round, 3 = atomicAdd (split-K), 4 = round.
// Kstride = row pitch of A and W; Klen = K handled by this CTA (blockIdx.z split).
#define SPITCH 36
#define TILEF  (128 * SPITCH)
#define BUFF   (2 * TILEF)
#define GEMM_SMEM (2 * BUFF * 4)       // 73728 bytes

template <int EPI>
__global__ __launch_bounds__(256, 2)
void gemm_tf32_kernel(const float* __restrict__ A, const float* __restrict__ W,
                      float* __restrict__ C, int M, int Nc, int Kstride, int Klen) {
    extern __shared__ float sm[];
    const int tid = threadIdx.x;
    const int wid = tid >> 5, lid = tid & 31;
    const int gid = lid >> 2, tig = lid & 3;
    const int wm = wid >> 2, wn = wid & 3;
    const int m0 = blockIdx.y * 128;
    const int n0 = blockIdx.x * 128;
    const int kbase = blockIdx.z * Klen;
    const int T = Klen >> 5;

    float acc[4][4][4];
    #pragma unroll
    for (int i = 0; i < 4; i++)
        #pragma unroll
        for (int j = 0; j < 4; j++)
            #pragma unroll
            for (int c = 0; c < 4; c++) acc[i][j][c] = 0.f;

    const uint32_t smb = smem_u32(sm);

    auto load_tiles = [&](int buf, int k0) {
        uint32_t base = smb + (uint32_t)buf * (BUFF * 4);
        #pragma unroll
        for (int t = 0; t < 4; t++) {
            int c = tid + t * 256;
            int row = c >> 3;
            int cb = (c & 7) * 16;
            uint32_t soff = (uint32_t)row * (SPITCH * 4) + cb;
            CP_ASYNC16(base + soff,
                       A + (size_t)(m0 + row) * Kstride + kbase + k0 + (cb >> 2));
            CP_ASYNC16(base + (uint32_t)(TILEF * 4) + soff,
                       W + (size_t)(n0 + row) * Kstride + kbase + k0 + (cb >> 2));
        }
    };

    load_tiles(0, 0);
    CP_COMMIT();

    for (int i = 0; i < T; i++) {
        const int cur = i & 1;
        if (i + 1 < T) {
            load_tiles(cur ^ 1, (i + 1) << 5);
            CP_COMMIT();
            cp_wait<1>();
        } else {
            cp_wait<0>();
        }
        __syncthreads();

        const float* As = sm + cur * BUFF;
        const float* Bs = As + TILEF;
        #pragma unroll
        for (int ks = 0; ks < 4; ks++) {
            const int k8 = ks * 8;
            float a[4][4], b[4][2];
            #pragma unroll
            for (int mi = 0; mi < 4; mi++) {
                const float* ap = As + (wm * 64 + mi * 16 + gid) * SPITCH + k8 + tig;
                a[mi][0] = ap[0];
                a[mi][1] = ap[8 * SPITCH];
                a[mi][2] = ap[4];
                a[mi][3] = ap[8 * SPITCH + 4];
            }
            #pragma unroll
            for (int nj = 0; nj < 4; nj++) {
                const float* bp = Bs + (wn * 32 + nj * 8 + gid) * SPITCH + k8 + tig;
                b[nj][0] = bp[0];
                b[nj][1] = bp[4];
            }
            #pragma unroll
            for (int mi = 0; mi < 4; mi++)
                #pragma unroll
                for (int nj = 0; nj < 4; nj++)
                    mma_tf32(acc[mi][nj], a[mi], b[nj]);
        }
        __syncthreads();
    }

    #pragma unroll
    for (int mi = 0; mi < 4; mi++) {
        const int mA = m0 + wm * 64 + mi * 16 + gid;
        const int mB = mA + 8;
        #pragma unroll
        for (int nj = 0; nj < 4; nj++) {
            const int col = n0 + wn * 32 + nj * 8 + tig * 2;
            float2 v0 = make_float2(acc[mi][nj][0], acc[mi][nj][1]);
            float2 v1 = make_float2(acc[mi][nj][2], acc[mi][nj][3]);
            if (EPI == 1) {
                v0.x = to_tf32(fmaxf(v0.x, 0.f)); v0.y = to_tf32(fmaxf(v0.y, 0.f));
                v1.x = to_tf32(fmaxf(v1.x, 0.f)); v1.y = to_tf32(fmaxf(v1.y, 0.f));
            } else if (EPI == 4) {
                v0.x = to_tf32(v0.x); v0.y = to_tf32(v0.y);
                v1.x = to_tf32(v1.x); v1.y = to_tf32(v1.y);
            }
            if (EPI == 3) {
                float* c0 = C + (size_t)mA * Nc + col;
                float* c1 = C + (size_t)mB * Nc + col;
                atomicAdd(c0, v0.x); atomicAdd(c0 + 1, v0.y);
                atomicAdd(c1, v1.x); atomicAdd(c1 + 1, v1.y);
            } else {
                *(float2*)(C + (size_t)mA * Nc + col) = v0;
                *(float2*)(C + (size_t)mB * Nc + col) = v1;
            }
        }
    }
}

// ---------------- tensor-core flash attention (tf32 mma) --------------------
// QKV already tf32. cp.async double-buffered K/V tiles.
// CTA: 64 q-rows for one (b,h); 4 warps, each m16 over full kv/d.
#define KPITCH 68
#define VPITCH 72
#define PPITCH 68
#define KBUF (64 * KPITCH)
#define VBUF (64 * VPITCH)
#define ATT_SMEM ((2 * KBUF + 2 * VBUF + 64 * PPITCH) * 4)  // 89088 B

__global__ __launch_bounds__(128, 2)
void attention_mma_kernel(const float* __restrict__ QKV,
                          const float* __restrict__ tab,
                          float* __restrict__ O) {
    extern __shared__ float smem[];
    float* Kb[2] = {smem, smem + KBUF};
    float* Vb[2] = {smem + 2 * KBUF, smem + 2 * KBUF + VBUF};
    float* Ps = smem + 2 * KBUF + 2 * VBUF;

    const int bh = blockIdx.y;
    const int b = bh >> 4, h = bh & 15;
    const int q0 = blockIdx.x * 64;
    const int tid = threadIdx.x;
    const int wid = tid >> 5, lid = tid & 31;
    const int gid = lid >> 2, tig = lid & 3;
    const uint32_t smb = smem_u32(smem);

    // Q fragments (A, m16 x k64) — already tf32
    float qf[8][4];
    {
        const float* Qb = QKV + (size_t)(b * SEQ + q0 + wid * 16 + gid) * QKV_N + h * D_KV;
        #pragma unroll
        for (int k = 0; k < 8; k++) {
            qf[k][0] = Qb[k * 8 + tig];
            qf[k][1] = Qb[8 * QKV_N + k * 8 + tig];
            qf[k][2] = Qb[k * 8 + tig + 4];
            qf[k][3] = Qb[8 * QKV_N + k * 8 + tig + 4];
        }
    }

    auto load_kv = [&](int buf, int k0) {
        const float* Kg = QKV + INNER + h * D_KV;
        const float* Vg = QKV + 2 * INNER + h * D_KV;
        uint32_t kb = smb + (uint32_t)(buf * KBUF) * 4;
        uint32_t vb = smb + (uint32_t)(2 * KBUF + buf * VBUF) * 4;
        #pragma unroll
        for (int t = 0; t < 8; t++) {
            int idx = tid + t * 128;           // 0..1023
            int row = idx >> 4;                // 0..63
            int c4 = (idx & 15) * 4;
            size_t gaddr = (size_t)(b * SEQ + k0 + row) * QKV_N + c4;
            CP_ASYNC16(kb + (uint32_t)(row * KPITCH + c4) * 4, Kg + gaddr);
            CP_ASYNC16(vb + (uint32_t)(row * VPITCH + c4) * 4, Vg + gaddr);
        }
    };

    float oacc[8][4];
    #pragma unroll
    for (int nj = 0; nj < 8; nj++)
        #pragma unroll
        for (int c = 0; c < 4; c++) oacc[nj][c] = 0.f;
    float m0 = -1e30f, m1 = -1e30f, l0 = 0.f, l1 = 0.f;

    load_kv(0, 0);
    CP_COMMIT();

    for (int it = 0; it < SEQ / 64; it++) {
        const int cur = it & 1;
        const int k0 = it * 64;
        if (it + 1 < SEQ / 64) {
            load_kv(cur ^ 1, k0 + 64);
            CP_COMMIT();
            cp_wait<1>();
        } else {
            cp_wait<0>();
        }
        __syncthreads();
        const float* Ks = Kb[cur];
        const float* Vs = Vb[cur];

        // S = Q @ K^T
        float sacc[8][4];
        #pragma unroll
        for (int nj = 0; nj < 8; nj++)
            #pragma unroll
            for (int c = 0; c < 4; c++) sacc[nj][c] = 0.f;
        #pragma unroll
        for (int k = 0; k < 8; k++) {
            #pragma unroll
            for (int nj = 0; nj < 8; nj++) {
                float bf[2];
                const float* kp = Ks + (nj * 8 + gid) * KPITCH + k * 8 + tig;
                bf[0] = kp[0];
                bf[1] = kp[4];
                mma_tf32(sacc[nj], qf[k], bf);
            }
        }

        // bias + online softmax (rows gid and gid+8)
        const float* bt = tab + h * TAB_LEN + 1023 + k0 - (q0 + wid * 16);
        float rx0 = -1e30f, rx1 = -1e30f;
        #pragma unroll
        for (int nj = 0; nj < 8; nj++) {
            int c = nj * 8 + 2 * tig;
            sacc[nj][0] += __ldg(bt + c - gid);
            sacc[nj][1] += __ldg(bt + c + 1 - gid);
            sacc[nj][2] += __ldg(bt + c - gid - 8);
            sacc[nj][3] += __ldg(bt + c + 1 - gid - 8);
            rx0 = fmaxf(rx0, fmaxf(sacc[nj][0], sacc[nj][1]));
            rx1 = fmaxf(rx1, fmaxf(sacc[nj][2], sacc[nj][3]));
        }
        rx0 = fmaxf(rx0, __shfl_xor_sync(0xFFFFFFFFu, rx0, 1));
        rx0 = fmaxf(rx0, __shfl_xor_sync(0xFFFFFFFFu, rx0, 2));
        rx1 = fmaxf(rx1, __shfl_xor_sync(0xFFFFFFFFu, rx1, 1));
        rx1 = fmaxf(rx1, __shfl_xor_sync(0xFFFFFFFFu, rx1, 2));
        float mn0 = fmaxf(m0, rx0), mn1 = fmaxf(m1, rx1);
        float sc0 = __expf(m0 - mn0), sc1 = __expf(m1 - mn1);
        m0 = mn0; m1 = mn1;

        float rs0 = 0.f, rs1 = 0.f;
        float* pw0 = Ps + (wid * 16 + gid) * PPITCH;
        float* pw1 = pw0 + 8 * PPITCH;
        #pragma unroll
        for (int nj = 0; nj < 8; nj++) {
            int c = nj * 8 + 2 * tig;
            float p0 = __expf(sacc[nj][0] - m0);
            float p1 = __expf(sacc[nj][1] - m0);
            float p2 = __expf(sacc[nj][2] - m1);
            float p3 = __expf(sacc[nj][3] - m1);
            rs0 += p0 + p1; rs1 += p2 + p3;
            *(float2*)(pw0 + c) = make_float2(to_tf32(p0), to_tf32(p1));
            *(float2*)(pw1 + c) = make_float2(to_tf32(p2), to_tf32(p3));
        }
        rs0 += __shfl_xor_sync(0xFFFFFFFFu, rs0, 1);
        rs0 += __shfl_xor_sync(0xFFFFFFFFu, rs0, 2);
        rs1 += __shfl_xor_sync(0xFFFFFFFFu, rs1, 1);
        rs1 += __shfl_xor_sync(0xFFFFFFFFu, rs1, 2);
        l0 = l0 * sc0 + rs0;
        l1 = l1 * sc1 + rs1;
        #pragma unroll
        for (int nj = 0; nj < 8; nj++) {
            oacc[nj][0] *= sc0; oacc[nj][1] *= sc0;
            oacc[nj][2] *= sc1; oacc[nj][3] *= sc1;
        }
        __syncwarp();

        // O += P @ V
        #pragma unroll
        for (int k = 0; k < 8; k++) {
            float af[4];
            const float* pp = Ps + (wid * 16 + gid) * PPITCH + k * 8 + tig;
            af[0] = pp[0];
            af[1] = pp[8 * PPITCH];
            af[2] = pp[4];
            af[3] = pp[8 * PPITCH + 4];
            #pragma unroll
            for (int nj = 0; nj < 8; nj++) {
                float bf[2];
                const float* vp = Vs + (k * 8 + tig) * VPITCH + nj * 8 + gid;
                bf[0] = vp[0];
                bf[1] = vp[4 * VPITCH];
                mma_tf32(oacc[nj], af, bf);
            }
        }
        __syncthreads();   // release cur buffer for next cp.async round
    }

    float i0 = 1.f / l0, i1 = 1.f / l1;
    float* ob = O + (size_t)(b * SEQ + q0 + wid * 16 + gid) * INNER + h * D_KV;
    #pragma unroll
    for (int nj = 0; nj < 8; nj++) {
        int c = nj * 8 + 2 * tig;
        *(float2*)(ob + c) = make_float2(to_tf32(oacc[nj][0] * i0),
                                         to_tf32(oacc[nj][1] * i0));
        *(float2*)(ob + 8 * INNER + c) = make_float2(to_tf32(oacc[nj][2] * i1),
                                                     to_tf32(oacc[nj][3] * i1));
    }
}

// ---------------- launch -----------------------------------------------------
extern "C" void kernel_launch(void* const* d_in, const int* in_sizes, int n_in,
                              void* d_out, int out_size) {
    const float* hidden  = (const float*)d_in[0];
    const float* ln1_w   = (const float*)d_in[1];
    const float* wq      = (const float*)d_in[2];
    const float* wk      = (const float*)d_in[3];
    const float* wv      = (const float*)d_in[4];
    const float* wo      = (const float*)d_in[5];
    const float* relbias = (const float*)d_in[6];
    const float* ln2_w   = (const float*)d_in[7];
    const float* wi      = (const float*)d_in[8];
    const float* wo_ff   = (const float*)d_in[9];
    float* out = (float*)d_out;

    float *px, *pqkv, *pctx, *ph, *py, *pmid, *pbias;
    float *pwqkv, *pwo, *pwi, *pwoff;
    cudaGetSymbolAddress((void**)&px,    g_x);
    cudaGetSymbolAddress((void**)&pqkv,  g_qkv);
    cudaGetSymbolAddress((void**)&pctx,  g_ctx);
    cudaGetSymbolAddress((void**)&ph,    g_h);
    cudaGetSymbolAddress((void**)&py,    g_y);
    cudaGetSymbolAddress((void**)&pmid,  g_mid);
    cudaGetSymbolAddress((void**)&pbias, g_bias);
    cudaGetSymbolAddress((void**)&pwqkv, g_wqkv_r);
    cudaGetSymbolAddress((void**)&pwo,   g_wo_r);
    cudaGetSymbolAddress((void**)&pwi,   g_wi_r);
    cudaGetSymbolAddress((void**)&pwoff, g_woff_r);

    cudaFuncSetAttribute(gemm_tf32_kernel<0>, cudaFuncAttributeMaxDynamicSharedMemorySize, GEMM_SMEM);
    cudaFuncSetAttribute(gemm_tf32_kernel<1>, cudaFuncAttributeMaxDynamicSharedMemorySize, GEMM_SMEM);
    cudaFuncSetAttribute(gemm_tf32_kernel<3>, cudaFuncAttributeMaxDynamicSharedMemorySize, GEMM_SMEM);
    cudaFuncSetAttribute(gemm_tf32_kernel<4>, cudaFuncAttributeMaxDynamicSharedMemorySize, GEMM_SMEM);
    cudaFuncSetAttribute(attention_mma_kernel, cudaFuncAttributeMaxDynamicSharedMemorySize, ATT_SMEM);

    // weight prepass: round to tf32 once (wq/wk/wv packed)
    const int n4s = (INNER * D_MODEL) / 4;
    const int n4b = (D_FF * D_MODEL) / 4;
    round_tf32_kernel<<<n4s / 256, 256>>>((const float4*)wq, (float4*)pwqkv, n4s);
    round_tf32_kernel<<<n4s / 256, 256>>>((const float4*)wk,
        (float4*)(pwqkv + (size_t)INNER * D_MODEL), n4s);
    round_tf32_kernel<<<n4s / 256, 256>>>((const float4*)wv,
        (float4*)(pwqkv + (size_t)2 * INNER * D_MODEL), n4s);
    round_tf32_kernel<<<n4s / 256, 256>>>((const float4*)wo, (float4*)pwo, n4s);
    round_tf32_kernel<<<n4b / 256, 256>>>((const float4*)wi, (float4*)pwi, n4b);
    round_tf32_kernel<<<n4b / 256, 256>>>((const float4*)wo_ff, (float4*)pwoff, n4b);

    bias_table_kernel<<<(TAB_LEN + 255) / 256, 256>>>(relbias, pbias);
    rmsnorm_kernel<<<M_ROWS, 256>>>(hidden, ln1_w, px);

    // QKV projection [2048x1024] @ [3072x1024]^T, output rounded to tf32
    gemm_tf32_kernel<4><<<dim3(QKV_N / 128, M_ROWS / 128), 256, GEMM_SMEM>>>(
        px, pwqkv, pqkv, M_ROWS, QKV_N, D_MODEL, D_MODEL);

    // tensor-core attention (rounds ctx at epilogue)
    attention_mma_kernel<<<dim3(SEQ / 64, BATCH * N_HEADS), 128, ATT_SMEM>>>(
        pqkv, pbias, pctx);

    // h = hidden + ctx @ wo^T : init h=hidden, split-K2 atomic GEMM
    cudaMemcpyAsync(ph, hidden, (size_t)M_ROWS * D_MODEL * sizeof(float),
                    cudaMemcpyDeviceToDevice);
    gemm_tf32_kernel<3><<<dim3(D_MODEL / 128, M_ROWS / 128, 2), 256, GEMM_SMEM>>>(
        pctx, pwo, ph, M_ROWS, D_MODEL, INNER, INNER / 2);

    rmsnorm_kernel<<<M_ROWS, 256>>>(ph, ln2_w, py);

    // mid = relu(y @ wi^T) (rounded)
    gemm_tf32_kernel<1><<<dim3(D_FF / 128, M_ROWS / 128), 256, GEMM_SMEM>>>(
        py, pwi, pmid, M_ROWS, D_FF, D_MODEL, D_MODEL);

    // out = h + mid @ wo_ff^T : init out=h, split-K2 atomic GEMM
    cudaMemcpyAsync(out, ph, (size_t)M_ROWS * D_MODEL * sizeof(float),
                    cudaMemcpyDeviceToDevice);
    gemm_tf32_kernel<3><<<dim3(D_MODEL / 128, M_ROWS / 128, 2), 256, GEMM_SMEM>>>(
        pmid, pwoff, out, M_ROWS, D_MODEL, D_FF, D_FF / 2);
}

// round 10
// speedup vs baseline: 3.7786x; 1.0838x over previous
#include <cuda_runtime.h>
#include <cuda_bf16.h>
#include <math.h>
#include <stdint.h>

#define D_MODEL 1024
#define N_HEADS 16
#define D_KV    64
#define INNER   1024
#define QKV_N   3072
#define D_FF    4096
#define SEQ     1024
#define BATCH   2
#define M_ROWS  (BATCH * SEQ)   // 2048
#define TAB_LEN 2047            // rel in [-1023, 1023]

// ---------------- scratch (device globals: no allocation allowed) ----------
__device__ float g_x   [M_ROWS * D_MODEL];
__device__ float g_qkv [M_ROWS * QKV_N];
__device__ float g_ctx [M_ROWS * INNER];
__device__ float g_h   [M_ROWS * D_MODEL];
__device__ float g_y   [M_ROWS * D_MODEL];
__device__ float g_mid [M_ROWS * D_FF];
__device__ float g_bias[N_HEADS * TAB_LEN];
// tf32-rounded weights (wq/wk/wv packed)
__device__ float g_wqkv_r[QKV_N * D_MODEL];
__device__ float g_wo_r  [D_MODEL * INNER];
__device__ float g_wi_r  [D_FF * D_MODEL];
__device__ float g_woff_r[D_MODEL * D_FF];

// ---------------- helpers ----------------------------------------------------
__device__ __forceinline__ float to_tf32(float x) {
    float r;
    asm("cvt.rna.tf32.f32 %0, %1;" : "=f"(r) : "f"(x));
    return r;
}
__device__ __forceinline__ uint32_t smem_u32(const void* p) {
    uint32_t a;
    asm("{ .reg .u64 t; cvta.to.shared.u64 t, %1; cvt.u32.u64 %0, t; }"
        : "=r"(a) : "l"(p));
    return a;
}
#define CP_ASYNC16(sm, gp) \
    asm volatile("cp.async.cg.shared.global [%0], [%1], 16;" :: "r"(sm), "l"(gp))
#define CP_COMMIT() asm volatile("cp.async.commit_group;" ::: "memory")
template <int NN>
__device__ __forceinline__ void cp_wait() {
    asm volatile("cp.async.wait_group %0;" :: "n"(NN) : "memory");
}

__device__ __forceinline__ void mma_tf32(float* d, const float* a, const float* b) {
    asm volatile(
        "mma.sync.aligned.m16n8k8.row.col.f32.tf32.tf32.f32 "
        "{%0,%1,%2,%3}, {%4,%5,%6,%7}, {%8,%9}, {%0,%1,%2,%3};"
        : "+f"(d[0]), "+f"(d[1]), "+f"(d[2]), "+f"(d[3])
        : "r"(__float_as_uint(a[0])), "r"(__float_as_uint(a[1])),
          "r"(__float_as_uint(a[2])), "r"(__float_as_uint(a[3])),
          "r"(__float_as_uint(b[0])), "r"(__float_as_uint(b[1])));
}
__device__ __forceinline__ void mma_tf32u(float* d, const uint32_t* a, const uint32_t* b) {
    asm volatile(
        "mma.sync.aligned.m16n8k8.row.col.f32.tf32.tf32.f32 "
        "{%0,%1,%2,%3}, {%4,%5,%6,%7}, {%8,%9}, {%0,%1,%2,%3};"
        : "+f"(d[0]), "+f"(d[1]), "+f"(d[2]), "+f"(d[3])
        : "r"(a[0]), "r"(a[1]), "r"(a[2]), "r"(a[3]), "r"(b[0]), "r"(b[1]));
}
// tf32 fragment load: 8x4-f32 tile == 8x8-b16 tile; lane l <- (row l/4, col l%4)
__device__ __forceinline__ void ldsm_x4(uint32_t addr, uint32_t* r) {
    asm volatile("ldmatrix.sync.aligned.m8n8.x4.shared.b16 {%0,%1,%2,%3}, [%4];"
        : "=r"(r[0]), "=r"(r[1]), "=r"(r[2]), "=r"(r[3]) : "r"(addr));
}

// ---------------- fused weight rounding (one launch) ------------------------
#define N4S ((INNER * D_MODEL) / 4)   // 262144
#define N4B ((D_FF * D_MODEL) / 4)    // 1048576
#define N4TOT (4 * N4S + 2 * N4B)     // 3145728
__global__ void round_all_kernel(const float4* __restrict__ wq,
                                 const float4* __restrict__ wk,
                                 const float4* __restrict__ wv,
                                 const float4* __restrict__ wo,
                                 const float4* __restrict__ wi,
                                 const float4* __restrict__ woff,
                                 float4* __restrict__ dqkv,
                                 float4* __restrict__ dwo,
                                 float4* __restrict__ dwi,
                                 float4* __restrict__ dwoff) {
    int i = blockIdx.x * blockDim.x + threadIdx.x;
    if (i >= N4TOT) return;
    const float4* src;
    float4* dst;
    int off;
    if (i < 3 * N4S)      { int s = i / N4S; off = i - s * N4S;
                            src = (s == 0) ? wq : (s == 1) ? wk : wv;
                            dst = dqkv + (size_t)s * N4S; }
    else if (i < 4 * N4S) { off = i - 3 * N4S; src = wo;   dst = dwo; }
    else if (i < 4 * N4S + N4B) { off = i - 4 * N4S; src = wi; dst = dwi; }
    else                  { off = i - 4 * N4S - N4B; src = woff; dst = dwoff; }
    float4 v = src[off];
    v.x = to_tf32(v.x); v.y = to_tf32(v.y);
    v.z = to_tf32(v.z); v.w = to_tf32(v.w);
    dst[off] = v;
}

// ---------------- RMSNorm (T5), output rounded to tf32 ----------------------
__global__ void rmsnorm_kernel(const float* __restrict__ in,
                               const float* __restrict__ w,
                               float* __restrict__ out) {
    int row = blockIdx.x;
    const float4* inr = (const float4*)(in + (size_t)row * D_MODEL);
    float4 v = inr[threadIdx.x];
    float ss = v.x * v.x + v.y * v.y + v.z * v.z + v.w * v.w;
    #pragma unroll
    for (int o = 16; o; o >>= 1) ss += __shfl_xor_sync(0xFFFFFFFFu, ss, o);
    __shared__ float sred[8];
    if ((threadIdx.x & 31) == 0) sred[threadIdx.x >> 5] = ss;
    __syncthreads();
    float total = 0.f;
    #pragma unroll
    for (int i = 0; i < 8; i++) total += sred[i];
    float scale = rsqrtf(total * (1.0f / D_MODEL) + 1e-6f);
    float4 wv = ((const float4*)w)[threadIdx.x];
    float4 o4 = make_float4(to_tf32(v.x * scale * wv.x), to_tf32(v.y * scale * wv.y),
                            to_tf32(v.z * scale * wv.z), to_tf32(v.w * scale * wv.w));
    ((float4*)(out + (size_t)row * D_MODEL))[threadIdx.x] = o4;
}

// ---------------- relative position bias table ------------------------------
__global__ void bias_table_kernel(const float* __restrict__ rel_bias,
                                  float* __restrict__ tab) {
    int i = blockIdx.x * blockDim.x + threadIdx.x;
    if (i >= TAB_LEN) return;
    int rel = i - 1023;
    int rb = (rel > 0) ? 16 : 0;
    int rp = rel < 0 ? -rel : rel;
    int val;
    if (rp < 8) {
        val = rp;
    } else {
        float t = logf((float)rp * 0.125f) * (8.0f / 2.772588722239781f);
        int large = 8 + (int)t;
        val = large < 15 ? large : 15;
    }
    int bucket = rb + val;
    #pragma unroll
    for (int h = 0; h < N_HEADS; h++)
        tab[h * TAB_LEN + i] = rel_bias[bucket * N_HEADS + h];
}

// ---------------- tf32 mma.sync GEMM with ldmatrix fragments ----------------
// C[M,N] = A[M,K] @ W[N,K]^T. Inputs pre-rounded to tf32.
// EPI: 1 = relu + round, 3 = atomicAdd (split-K), 4 = round.
#define SPITCH 36
#define TILEF  (128 * SPITCH)
#define BUFF   (2 * TILEF)
#define GEMM_SMEM (2 * BUFF * 4)       // 73728 bytes

template <int EPI>
__global__ __launch_bounds__(256, 2)
void gemm_tf32_kernel(const float* __restrict__ A, const float* __restrict__ W,
                      float* __restrict__ C, int M, int Nc, int Kstride, int Klen) {
    extern __shared__ float sm[];
    const int tid = threadIdx.x;
    const int wid = tid >> 5, lid = tid & 31;
    const int gid = lid >> 2, tig = lid & 3;
    const int wm = wid >> 2, wn = wid & 3;
    const int m0 = blockIdx.y * 128;
    const int n0 = blockIdx.x * 128;
    const int kbase = blockIdx.z * Klen;
    const int T = Klen >> 5;

    float acc[4][4][4];
    #pragma unroll
    for (int i = 0; i < 4; i++)
        #pragma unroll
        for (int j = 0; j < 4; j++)
            #pragma unroll
            for (int c = 0; c < 4; c++) acc[i][j][c] = 0.f;

    const uint32_t smb = smem_u32(sm);

    // ldmatrix per-lane addresses (byte offsets inside a tile)
    const int lg = lid >> 3, r8 = lid & 7;
    // A tiles for (mi,ks): order m0-7/k0-3, m8-15/k0-3, m0-7/k4-7, m8-15/k4-7
    const uint32_t aoff = ((uint32_t)(wm * 64 + (lg & 1) * 8 + r8) * SPITCH
                           + (lg >> 1) * 4) * 4;
    // B tiles for nj-pair p: order n0-7/k0-3, n0-7/k4-7, n8-15/k0-3, n8-15/k4-7
    const uint32_t boff = ((uint32_t)(wn * 32 + (lg >> 1) * 8 + r8) * SPITCH
                           + (lg & 1) * 4) * 4 + (uint32_t)TILEF * 4;

    auto load_tiles = [&](int buf, int k0) {
        uint32_t base = smb + (uint32_t)buf * (BUFF * 4);
        #pragma unroll
        for (int t = 0; t < 4; t++) {
            int c = tid + t * 256;
            int row = c >> 3;
            int cb = (c & 7) * 16;
            uint32_t soff = (uint32_t)row * (SPITCH * 4) + cb;
            CP_ASYNC16(base + soff,
                       A + (size_t)(m0 + row) * Kstride + kbase + k0 + (cb >> 2));
            CP_ASYNC16(base + (uint32_t)(TILEF * 4) + soff,
                       W + (size_t)(n0 + row) * Kstride + kbase + k0 + (cb >> 2));
        }
    };

    load_tiles(0, 0);
    CP_COMMIT();

    for (int i = 0; i < T; i++) {
        const int cur = i & 1;
        if (i + 1 < T) {
            load_tiles(cur ^ 1, (i + 1) << 5);
            CP_COMMIT();
            cp_wait<1>();
        } else {
            cp_wait<0>();
        }
        __syncthreads();

        const uint32_t base = smb + (uint32_t)cur * (BUFF * 4);
        #pragma unroll
        for (int ks = 0; ks < 4; ks++) {
            const uint32_t kso = (uint32_t)(ks * 8) * 4;
            uint32_t a[4][4], bb[2][4];
            #pragma unroll
            for (int mi = 0; mi < 4; mi++)
                ldsm_x4(base + aoff + (uint32_t)(mi * 16 * SPITCH) * 4 + kso, a[mi]);
            #pragma unroll
            for (int p = 0; p < 2; p++)
                ldsm_x4(base + boff + (uint32_t)(p * 16 * SPITCH) * 4 + kso, bb[p]);
            #pragma unroll
            for (int mi = 0; mi < 4; mi++) {
                mma_tf32u(acc[mi][0], a[mi], bb[0]);
                mma_tf32u(acc[mi][1], a[mi], bb[0] + 2);
                mma_tf32u(acc[mi][2], a[mi], bb[1]);
                mma_tf32u(acc[mi][3], a[mi], bb[1] + 2);
            }
        }
        __syncthreads();
    }

    #pragma unroll
    for (int mi = 0; mi < 4; mi++) {
        const int mA = m0 + wm * 64 + mi * 16 + gid;
        const int mB = mA + 8;
        #pragma unroll
        for (int nj = 0; nj < 4; nj++) {
            const int col = n0 + wn * 32 + nj * 8 + tig * 2;
            float2 v0 = make_float2(acc[mi][nj][0], acc[mi][nj][1]);
            float2 v1 = make_float2(acc[mi][nj][2], acc[mi][nj][3]);
            if (EPI == 1) {
                v0.x = to_tf32(fmaxf(v0.x, 0.f)); v0.y = to_tf32(fmaxf(v0.y, 0.f));
                v1.x = to_tf32(fmaxf(v1.x, 0.f)); v1.y = to_tf32(fmaxf(v1.y, 0.f));
            } else if (EPI == 4) {
                v0.x = to_tf32(v0.x); v0.y = to_tf32(v0.y);
                v1.x = to_tf32(v1.x); v1.y = to_tf32(v1.y);
            }
            if (EPI == 3) {
                float* c0 = C + (size_t)mA * Nc + col;
                float* c1 = C + (size_t)mB * Nc + col;
                atomicAdd(c0, v0.x); atomicAdd(c0 + 1, v0.y);
                atomicAdd(c1, v1.x); atomicAdd(c1 + 1, v1.y);
            } else {
                *(float2*)(C + (size_t)mA * Nc + col) = v0;
                *(float2*)(C + (size_t)mB * Nc + col) = v1;
            }
        }
    }
}

// ---------------- tensor-core flash attention (tf32 mma) --------------------
#define KPITCH 68
#define VPITCH 72
#define PPITCH 68
#define KBUF (64 * KPITCH)
#define VBUF (64 * VPITCH)
#define ATT_SMEM ((2 * KBUF + 2 * VBUF + 64 * PPITCH) * 4)  // 89088 B

__global__ __launch_bounds__(128, 2)
void attention_mma_kernel(const float* __restrict__ QKV,
                          const float* __restrict__ tab,
                          float* __restrict__ O) {
    extern __shared__ float smem[];
    float* Kb[2] = {smem, smem + KBUF};
    float* Vb[2] = {smem + 2 * KBUF, smem + 2 * KBUF + VBUF};
    float* Ps = smem + 2 * KBUF + 2 * VBUF;

    const int bh = blockIdx.y;
    const int b = bh >> 4, h = bh & 15;
    const int q0 = blockIdx.x * 64;
    const int tid = threadIdx.x;
    const int wid = tid >> 5, lid = tid & 31;
    const int gid = lid >> 2, tig = lid & 3;
    const uint32_t smb = smem_u32(smem);

    float qf[8][4];
    {
        const float* Qb = QKV + (size_t)(b * SEQ + q0 + wid * 16 + gid) * QKV_N + h * D_KV;
        #pragma unroll
        for (int k = 0; k < 8; k++) {
            qf[k][0] = Qb[k * 8 + tig];
            qf[k][1] = Qb[8 * QKV_N + k * 8 + tig];
            qf[k][2] = Qb[k * 8 + tig + 4];
            qf[k][3] = Qb[8 * QKV_N + k * 8 + tig + 4];
        }
    }

    auto load_kv = [&](int buf, int k0) {
        const float* Kg = QKV + INNER + h * D_KV;
        const float* Vg = QKV + 2 * INNER + h * D_KV;
        uint32_t kb = smb + (uint32_t)(buf * KBUF) * 4;
        uint32_t vb = smb + (uint32_t)(2 * KBUF + buf * VBUF) * 4;
        #pragma unroll
        for (int t = 0; t < 8; t++) {
            int idx = tid + t * 128;
            int row = idx >> 4;
            int c4 = (idx & 15) * 4;
            size_t gaddr = (size_t)(b * SEQ + k0 + row) * QKV_N + c4;
            CP_ASYNC16(kb + (uint32_t)(row * KPITCH + c4) * 4, Kg + gaddr);
            CP_ASYNC16(vb + (uint32_t)(row * VPITCH + c4) * 4, Vg + gaddr);
        }
    };

    float oacc[8][4];
    #pragma unroll
    for (int nj = 0; nj < 8; nj++)
        #pragma unroll
        for (int c = 0; c < 4; c++) oacc[nj][c] = 0.f;
    float m0 = -1e30f, m1 = -1e30f, l0 = 0.f, l1 = 0.f;

    load_kv(0, 0);
    CP_COMMIT();

    for (int it = 0; it < SEQ / 64; it++) {
        const int cur = it & 1;
        const int k0 = it * 64;
        if (it + 1 < SEQ / 64) {
            load_kv(cur ^ 1, k0 + 64);
            CP_COMMIT();
            cp_wait<1>();
        } else {
            cp_wait<0>();
        }
        __syncthreads();
        const float* Ks = Kb[cur];
        const float* Vs = Vb[cur];

        float sacc[8][4];
        #pragma unroll
        for (int nj = 0; nj < 8; nj++)
            #pragma unroll
            for (int c = 0; c < 4; c++) sacc[nj][c] = 0.f;
        #pragma unroll
        for (int k = 0; k < 8; k++) {
            #pragma unroll
            for (int nj = 0; nj < 8; nj++) {
                float bf[2];
                const float* kp = Ks + (nj * 8 + gid) * KPITCH + k * 8 + tig;
                bf[0] = kp[0];
                bf[1] = kp[4];
                mma_tf32(sacc[nj], qf[k], bf);
            }
        }

        const float* bt = tab + h * TAB_LEN + 1023 + k0 - (q0 + wid * 16);
        float rx0 = -1e30f, rx1 = -1e30f;
        #pragma unroll
        for (int nj = 0; nj < 8; nj++) {
            int c = nj * 8 + 2 * tig;
            sacc[nj][0] += __ldg(bt + c - gid);
            sacc[nj][1] += __ldg(bt + c + 1 - gid);
            sacc[nj][2] += __ldg(bt + c - gid - 8);
            sacc[nj][3] += __ldg(bt + c + 1 - gid - 8);
            rx0 = fmaxf(rx0, fmaxf(sacc[nj][0], sacc[nj][1]));
            rx1 = fmaxf(rx1, fmaxf(sacc[nj][2], sacc[nj][3]));
        }
        rx0 = fmaxf(rx0, __shfl_xor_sync(0xFFFFFFFFu, rx0, 1));
        rx0 = fmaxf(rx0, __shfl_xor_sync(0xFFFFFFFFu, rx0, 2));
        rx1 = fmaxf(rx1, __shfl_xor_sync(0xFFFFFFFFu, rx1, 1));
        rx1 = fmaxf(rx1, __shfl_xor_sync(0xFFFFFFFFu, rx1, 2));
        float mn0 = fmaxf(m0, rx0), mn1 = fmaxf(m1, rx1);
        float sc0 = __expf(m0 - mn0), sc1 = __expf(m1 - mn1);
        m0 = mn0; m1 = mn1;

        float rs0 = 0.f, rs1 = 0.f;
        float* pw0 = Ps + (wid * 16 + gid) * PPITCH;
        float* pw1 = pw0 + 8 * PPITCH;
        #pragma unroll
        for (int nj = 0; nj < 8; nj++) {
            int c = nj * 8 + 2 * tig;
            float p0 = __expf(sacc[nj][0] - m0);
            float p1 = __expf(sacc[nj][1] - m0);
            float p2 = __expf(sacc[nj][2] - m1);
            float p3 = __expf(sacc[nj][3] - m1);
            rs0 += p0 + p1; rs1 += p2 + p3;
            *(float2*)(pw0 + c) = make_float2(to_tf32(p0), to_tf32(p1));
            *(float2*)(pw1 + c) = make_float2(to_tf32(p2), to_tf32(p3));
        }
        rs0 += __shfl_xor_sync(0xFFFFFFFFu, rs0, 1);
        rs0 += __shfl_xor_sync(0xFFFFFFFFu, rs0, 2);
        rs1 += __shfl_xor_sync(0xFFFFFFFFu, rs1, 1);
        rs1 += __shfl_xor_sync(0xFFFFFFFFu, rs1, 2);
        l0 = l0 * sc0 + rs0;
        l1 = l1 * sc1 + rs1;
        #pragma unroll
        for (int nj = 0; nj < 8; nj++) {
            oacc[nj][0] *= sc0; oacc[nj][1] *= sc0;
            oacc[nj][2] *= sc1; oacc[nj][3] *= sc1;
        }
        __syncwarp();

        #pragma unroll
        for (int k = 0; k < 8; k++) {
            float af[4];
            const float* pp = Ps + (wid * 16 + gid) * PPITCH + k * 8 + tig;
            af[0] = pp[0];
            af[1] = pp[8 * PPITCH];
            af[2] = pp[4];
            af[3] = pp[8 * PPITCH + 4];
            #pragma unroll
            for (int nj = 0; nj < 8; nj++) {
                float bf[2];
                const float* vp = Vs + (k * 8 + tig) * VPITCH + nj * 8 + gid;
                bf[0] = vp[0];
                bf[1] = vp[4 * VPITCH];
                mma_tf32(oacc[nj], af, bf);
            }
        }
        __syncthreads();
    }

    float i0 = 1.f / l0, i1 = 1.f / l1;
    float* ob = O + (size_t)(b * SEQ + q0 + wid * 16 + gid) * INNER + h * D_KV;
    #pragma unroll
    for (int nj = 0; nj < 8; nj++) {
        int c = nj * 8 + 2 * tig;
        *(float2*)(ob + c) = make_float2(to_tf32(oacc[nj][0] * i0),
                                         to_tf32(oacc[nj][1] * i0));
        *(float2*)(ob + 8 * INNER + c) = make_float2(to_tf32(oacc[nj][2] * i1),
                                                     to_tf32(oacc[nj][3] * i1));
    }
}

// ---------------- launch -----------------------------------------------------
extern "C" void kernel_launch(void* const* d_in, const int* in_sizes, int n_in,
                              void* d_out, int out_size) {
    const float* hidden  = (const float*)d_in[0];
    const float* ln1_w   = (const float*)d_in[1];
    const float* wq      = (const float*)d_in[2];
    const float* wk      = (const float*)d_in[3];
    const float* wv      = (const float*)d_in[4];
    const float* wo      = (const float*)d_in[5];
    const float* relbias = (const float*)d_in[6];
    const float* ln2_w   = (const float*)d_in[7];
    const float* wi      = (const float*)d_in[8];
    const float* wo_ff   = (const float*)d_in[9];
    float* out = (float*)d_out;

    float *px, *pqkv, *pctx, *ph, *py, *pmid, *pbias;
    float *pwqkv, *pwo, *pwi, *pwoff;
    cudaGetSymbolAddress((void**)&px,    g_x);
    cudaGetSymbolAddress((void**)&pqkv,  g_qkv);
    cudaGetSymbolAddress((void**)&pctx,  g_ctx);
    cudaGetSymbolAddress((void**)&ph,    g_h);
    cudaGetSymbolAddress((void**)&py,    g_y);
    cudaGetSymbolAddress((void**)&pmid,  g_mid);
    cudaGetSymbolAddress((void**)&pbias, g_bias);
    cudaGetSymbolAddress((void**)&pwqkv, g_wqkv_r);
    cudaGetSymbolAddress((void**)&pwo,   g_wo_r);
    cudaGetSymbolAddress((void**)&pwi,   g_wi_r);
    cudaGetSymbolAddress((void**)&pwoff, g_woff_r);

    cudaFuncSetAttribute(gemm_tf32_kernel<1>, cudaFuncAttributeMaxDynamicSharedMemorySize, GEMM_SMEM);
    cudaFuncSetAttribute(gemm_tf32_kernel<3>, cudaFuncAttributeMaxDynamicSharedMemorySize, GEMM_SMEM);
    cudaFuncSetAttribute(gemm_tf32_kernel<4>, cudaFuncAttributeMaxDynamicSharedMemorySize, GEMM_SMEM);
    cudaFuncSetAttribute(attention_mma_kernel, cudaFuncAttributeMaxDynamicSharedMemorySize, ATT_SMEM);

    // 0: fused weight rounding (one launch)
    round_all_kernel<<<(N4TOT + 255) / 256, 256>>>(
        (const float4*)wq, (const float4*)wk, (const float4*)wv,
        (const float4*)wo, (const float4*)wi, (const float4*)wo_ff,
        (float4*)pwqkv, (float4*)pwo, (float4*)pwi, (float4*)pwoff);

    // 1,2
    bias_table_kernel<<<(TAB_LEN + 255) / 256, 256>>>(relbias, pbias);
    rmsnorm_kernel<<<M_ROWS, 256>>>(hidden, ln1_w, px);

    // 3: QKV projection (rounded output)
    gemm_tf32_kernel<4><<<dim3(QKV_N / 128, M_ROWS / 128), 256, GEMM_SMEM>>>(
        px, pwqkv, pqkv, M_ROWS, QKV_N, D_MODEL, D_MODEL);

    // 4: attention
    attention_mma_kernel<<<dim3(SEQ / 64, BATCH * N_HEADS), 128, ATT_SMEM>>>(
        pqkv, pbias, pctx);

    // 5 (ncu target): h = hidden + ctx @ wo^T (split-K2 atomic)
    cudaMemcpyAsync(ph, hidden, (size_t)M_ROWS * D_MODEL * sizeof(float),
                    cudaMemcpyDeviceToDevice);
    gemm_tf32_kernel<3><<<dim3(D_MODEL / 128, M_ROWS / 128, 2), 256, GEMM_SMEM>>>(
        pctx, pwo, ph, M_ROWS, D_MODEL, INNER, INNER / 2);

    // 6
    rmsnorm_kernel<<<M_ROWS, 256>>>(ph, ln2_w, py);

    // 7: mid = relu(y @ wi^T)
    gemm_tf32_kernel<1><<<dim3(D_FF / 128, M_ROWS / 128), 256, GEMM_SMEM>>>(
        py, pwi, pmid, M_ROWS, D_FF, D_MODEL, D_MODEL);

    // 8: out = h + mid @ wo_ff^T (split-K2 atomic)
    cudaMemcpyAsync(out, ph, (size_t)M_ROWS * D_MODEL * sizeof(float),
                    cudaMemcpyDeviceToDevice);
    gemm_tf32_kernel<3><<<dim3(D_MODEL / 128, M_ROWS / 128, 2), 256, GEMM_SMEM>>>(
        pmid, pwoff, out, M_ROWS, D_MODEL, D_FF, D_FF / 2);
}

// round 12
// speedup vs baseline: 3.9785x; 1.0529x over previous
#include <cuda_runtime.h>
#include <cuda_bf16.h>
#include <math.h>
#include <stdint.h>

#define D_MODEL 1024
#define N_HEADS 16
#define D_KV    64
#define INNER   1024
#define QKV_N   3072
#define D_FF    4096
#define SEQ     1024
#define BATCH   2
#define M_ROWS  (BATCH * SEQ)   // 2048
#define TAB_LEN 2047            // rel in [-1023, 1023]

// ---------------- scratch (device globals: no allocation allowed) ----------
__device__ float g_x   [M_ROWS * D_MODEL];
__device__ float g_qkv [M_ROWS * QKV_N];
__device__ float g_ctx [M_ROWS * INNER];
__device__ float g_h   [M_ROWS * D_MODEL];
__device__ float g_y   [M_ROWS * D_MODEL];
__device__ float g_mid [M_ROWS * D_FF];
__device__ float g_bias[N_HEADS * TAB_LEN];
// tf32-rounded weights (wq/wk/wv packed)
__device__ float g_wqkv_r[QKV_N * D_MODEL];
__device__ float g_wo_r  [D_MODEL * INNER];
__device__ float g_wi_r  [D_FF * D_MODEL];
__device__ float g_woff_r[D_MODEL * D_FF];

// ---------------- helpers ----------------------------------------------------
__device__ __forceinline__ float to_tf32(float x) {
    float r;
    asm("cvt.rna.tf32.f32 %0, %1;" : "=f"(r) : "f"(x));
    return r;
}
__device__ __forceinline__ uint32_t smem_u32(const void* p) {
    uint32_t a;
    asm("{ .reg .u64 t; cvta.to.shared.u64 t, %1; cvt.u32.u64 %0, t; }"
        : "=r"(a) : "l"(p));
    return a;
}
#define CP_ASYNC16(sm, gp) \
    asm volatile("cp.async.cg.shared.global [%0], [%1], 16;" :: "r"(sm), "l"(gp))
#define CP_COMMIT() asm volatile("cp.async.commit_group;" ::: "memory")
template <int NN>
__device__ __forceinline__ void cp_wait() {
    asm volatile("cp.async.wait_group %0;" :: "n"(NN) : "memory");
}

__device__ __forceinline__ void mma_tf32u(float* d, const uint32_t* a, const uint32_t* b) {
    asm volatile(
        "mma.sync.aligned.m16n8k8.row.col.f32.tf32.tf32.f32 "
        "{%0,%1,%2,%3}, {%4,%5,%6,%7}, {%8,%9}, {%0,%1,%2,%3};"
        : "+f"(d[0]), "+f"(d[1]), "+f"(d[2]), "+f"(d[3])
        : "r"(a[0]), "r"(a[1]), "r"(a[2]), "r"(a[3]), "r"(b[0]), "r"(b[1]));
}
// tf32 fragment load: 8x4-f32 tile == 8x8-b16 tile; lane l <- (row l/4, col l%4)
__device__ __forceinline__ void ldsm_x4(uint32_t addr, uint32_t* r) {
    asm volatile("ldmatrix.sync.aligned.m8n8.x4.shared.b16 {%0,%1,%2,%3}, [%4];"
        : "=r"(r[0]), "=r"(r[1]), "=r"(r[2]), "=r"(r[3]) : "r"(addr));
}

// ---------------- fused weight rounding (one launch) ------------------------
#define N4S ((INNER * D_MODEL) / 4)
#define N4B ((D_FF * D_MODEL) / 4)
#define N4TOT (4 * N4S + 2 * N4B)
__global__ void round_all_kernel(const float4* __restrict__ wq,
                                 const float4* __restrict__ wk,
                                 const float4* __restrict__ wv,
                                 const float4* __restrict__ wo,
                                 const float4* __restrict__ wi,
                                 const float4* __restrict__ woff,
                                 float4* __restrict__ dqkv,
                                 float4* __restrict__ dwo,
                                 float4* __restrict__ dwi,
                                 float4* __restrict__ dwoff) {
    int i = blockIdx.x * blockDim.x + threadIdx.x;
    if (i >= N4TOT) return;
    const float4* src;
    float4* dst;
    int off;
    if (i < 3 * N4S)      { int s = i / N4S; off = i - s * N4S;
                            src = (s == 0) ? wq : (s == 1) ? wk : wv;
                            dst = dqkv + (size_t)s * N4S; }
    else if (i < 4 * N4S) { off = i - 3 * N4S; src = wo;   dst = dwo; }
    else if (i < 4 * N4S + N4B) { off = i - 4 * N4S; src = wi; dst = dwi; }
    else                  { off = i - 4 * N4S - N4B; src = woff; dst = dwoff; }
    float4 v = src[off];
    v.x = to_tf32(v.x); v.y = to_tf32(v.y);
    v.z = to_tf32(v.z); v.w = to_tf32(v.w);
    dst[off] = v;
}

// ---------------- RMSNorm (T5), output rounded to tf32 ----------------------
__global__ void rmsnorm_kernel(const float* __restrict__ in,
                               const float* __restrict__ w,
                               float* __restrict__ out) {
    int row = blockIdx.x;
    const float4* inr = (const float4*)(in + (size_t)row * D_MODEL);
    float4 v = inr[threadIdx.x];
    float ss = v.x * v.x + v.y * v.y + v.z * v.z + v.w * v.w;
    #pragma unroll
    for (int o = 16; o; o >>= 1) ss += __shfl_xor_sync(0xFFFFFFFFu, ss, o);
    __shared__ float sred[8];
    if ((threadIdx.x & 31) == 0) sred[threadIdx.x >> 5] = ss;
    __syncthreads();
    float total = 0.f;
    #pragma unroll
    for (int i = 0; i < 8; i++) total += sred[i];
    float scale = rsqrtf(total * (1.0f / D_MODEL) + 1e-6f);
    float4 wv = ((const float4*)w)[threadIdx.x];
    float4 o4 = make_float4(to_tf32(v.x * scale * wv.x), to_tf32(v.y * scale * wv.y),
                            to_tf32(v.z * scale * wv.z), to_tf32(v.w * scale * wv.w));
    ((float4*)(out + (size_t)row * D_MODEL))[threadIdx.x] = o4;
}

// ---------------- relative position bias table ------------------------------
__global__ void bias_table_kernel(const float* __restrict__ rel_bias,
                                  float* __restrict__ tab) {
    int i = blockIdx.x * blockDim.x + threadIdx.x;
    if (i >= TAB_LEN) return;
    int rel = i - 1023;
    int rb = (rel > 0) ? 16 : 0;
    int rp = rel < 0 ? -rel : rel;
    int val;
    if (rp < 8) {
        val = rp;
    } else {
        float t = logf((float)rp * 0.125f) * (8.0f / 2.772588722239781f);
        int large = 8 + (int)t;
        val = large < 15 ? large : 15;
    }
    int bucket = rb + val;
    #pragma unroll
    for (int h = 0; h < N_HEADS; h++)
        tab[h * TAB_LEN + i] = rel_bias[bucket * N_HEADS + h];
}

// ---------------- tf32 mma GEMM, 3-stage cp.async, 1 barrier/chunk ----------
// C[M,N] = A[M,K] @ W[N,K]^T. Inputs pre-rounded to tf32.
// EPI: 1 = relu + round, 3 = atomicAdd (split-K), 4 = round.
#define SPITCH 36
#define TILEF  (128 * SPITCH)
#define BUFF   (2 * TILEF)
#define GEMM_SMEM (3 * BUFF * 4)       // 110592 bytes (3 stages)

template <int EPI>
__global__ __launch_bounds__(256, 2)
void gemm_tf32_kernel(const float* __restrict__ A, const float* __restrict__ W,
                      float* __restrict__ C, int M, int Nc, int Kstride, int Klen) {
    extern __shared__ float sm[];
    const int tid = threadIdx.x;
    const int wid = tid >> 5, lid = tid & 31;
    const int gid = lid >> 2, tig = lid & 3;
    const int wm = wid >> 2, wn = wid & 3;
    const int m0 = blockIdx.y * 128;
    const int n0 = blockIdx.x * 128;
    const int kbase = blockIdx.z * Klen;
    const int T = Klen >> 5;

    float acc[4][4][4];
    #pragma unroll
    for (int i = 0; i < 4; i++)
        #pragma unroll
        for (int j = 0; j < 4; j++)
            #pragma unroll
            for (int c = 0; c < 4; c++) acc[i][j][c] = 0.f;

    const uint32_t smb = smem_u32(sm);

    const int lg = lid >> 3, r8 = lid & 7;
    const uint32_t aoff = ((uint32_t)(wm * 64 + (lg & 1) * 8 + r8) * SPITCH
                           + (lg >> 1) * 4) * 4;
    const uint32_t boff = ((uint32_t)(wn * 32 + (lg >> 1) * 8 + r8) * SPITCH
                           + (lg & 1) * 4) * 4 + (uint32_t)TILEF * 4;

    auto load_tiles = [&](int buf, int k0) {
        uint32_t base = smb + (uint32_t)buf * (BUFF * 4);
        #pragma unroll
        for (int t = 0; t < 4; t++) {
            int c = tid + t * 256;
            int row = c >> 3;
            int cb = (c & 7) * 16;
            uint32_t soff = (uint32_t)row * (SPITCH * 4) + cb;
            CP_ASYNC16(base + soff,
                       A + (size_t)(m0 + row) * Kstride + kbase + k0 + (cb >> 2));
            CP_ASYNC16(base + (uint32_t)(TILEF * 4) + soff,
                       W + (size_t)(n0 + row) * Kstride + kbase + k0 + (cb >> 2));
        }
    };

    load_tiles(0, 0);
    CP_COMMIT();
    load_tiles(1, 32);
    CP_COMMIT();

    int stage = 0;
    for (int i = 0; i < T; i++) {
        if (i < T - 1) cp_wait<1>(); else cp_wait<0>();
        __syncthreads();
        if (i + 2 < T) {
            int nst = stage + 2; if (nst >= 3) nst -= 3;
            load_tiles(nst, (i + 2) << 5);
            CP_COMMIT();
        }

        const uint32_t base = smb + (uint32_t)stage * (BUFF * 4);
        #pragma unroll
        for (int ks = 0; ks < 4; ks++) {
            const uint32_t kso = (uint32_t)(ks * 8) * 4;
            uint32_t a[4][4], bb[2][4];
            #pragma unroll
            for (int mi = 0; mi < 4; mi++)
                ldsm_x4(base + aoff + (uint32_t)(mi * 16 * SPITCH) * 4 + kso, a[mi]);
            #pragma unroll
            for (int p = 0; p < 2; p++)
                ldsm_x4(base + boff + (uint32_t)(p * 16 * SPITCH) * 4 + kso, bb[p]);
            #pragma unroll
            for (int mi = 0; mi < 4; mi++) {
                mma_tf32u(acc[mi][0], a[mi], bb[0]);
                mma_tf32u(acc[mi][1], a[mi], bb[0] + 2);
                mma_tf32u(acc[mi][2], a[mi], bb[1]);
                mma_tf32u(acc[mi][3], a[mi], bb[1] + 2);
            }
        }
        stage = (stage + 1 == 3) ? 0 : stage + 1;
    }

    #pragma unroll
    for (int mi = 0; mi < 4; mi++) {
        const int mA = m0 + wm * 64 + mi * 16 + gid;
        const int mB = mA + 8;
        #pragma unroll
        for (int nj = 0; nj < 4; nj++) {
            const int col = n0 + wn * 32 + nj * 8 + tig * 2;
            float2 v0 = make_float2(acc[mi][nj][0], acc[mi][nj][1]);
            float2 v1 = make_float2(acc[mi][nj][2], acc[mi][nj][3]);
            if (EPI == 1) {
                v0.x = to_tf32(fmaxf(v0.x, 0.f)); v0.y = to_tf32(fmaxf(v0.y, 0.f));
                v1.x = to_tf32(fmaxf(v1.x, 0.f)); v1.y = to_tf32(fmaxf(v1.y, 0.f));
            } else if (EPI == 4) {
                v0.x = to_tf32(v0.x); v0.y = to_tf32(v0.y);
                v1.x = to_tf32(v1.x); v1.y = to_tf32(v1.y);
            }
            if (EPI == 3) {
                float* c0 = C + (size_t)mA * Nc + col;
                float* c1 = C + (size_t)mB * Nc + col;
                atomicAdd(c0, v0.x); atomicAdd(c0 + 1, v0.y);
                atomicAdd(c1, v1.x); atomicAdd(c1 + 1, v1.y);
            } else {
                *(float2*)(C + (size_t)mA * Nc + col) = v0;
                *(float2*)(C + (size_t)mB * Nc + col) = v1;
            }
        }
    }
}

// ---------------- tensor-core flash attention (tf32 mma + ldmatrix) ---------
#define KPITCH 68
#define VPITCH 72
#define PPITCH 68
#define KBUF (64 * KPITCH)
#define VBUF (64 * VPITCH)
#define ATT_SMEM ((2 * KBUF + 2 * VBUF + 64 * PPITCH) * 4)  // 89088 B

__global__ __launch_bounds__(128, 2)
void attention_mma_kernel(const float* __restrict__ QKV,
                          const float* __restrict__ tab,
                          float* __restrict__ O) {
    extern __shared__ float smem[];
    const float* Vbp[2] = {smem + 2 * KBUF, smem + 2 * KBUF + VBUF};
    float* Ps = smem + 2 * KBUF + 2 * VBUF;

    const int bh = blockIdx.y;
    const int b = bh >> 4, h = bh & 15;
    const int q0 = blockIdx.x * 64;
    const int tid = threadIdx.x;
    const int wid = tid >> 5, lid = tid & 31;
    const int gid = lid >> 2, tig = lid & 3;
    const int lg = lid >> 3, r8 = lid & 7;
    const uint32_t smb = smem_u32(smem);

    // ldmatrix per-lane addresses (full shared addresses incl. smb!)
    // K (B-frag): tiles (n0-7,klo),(n0-7,khi),(n8-15,klo),(n8-15,khi)
    const uint32_t kboff = ((uint32_t)((lg >> 1) * 8 + r8) * KPITCH + (lg & 1) * 4) * 4;
    // P (A-frag): tiles (m0-7,klo),(m8-15,klo),(m0-7,khi),(m8-15,khi)
    const uint32_t paoff = smb
        + ((uint32_t)(wid * 16 + (lg & 1) * 8 + r8) * PPITCH + (lg >> 1) * 4) * 4
        + (uint32_t)(2 * KBUF + 2 * VBUF) * 4;

    // Q fragments (already tf32)
    uint32_t qfu[8][4];
    {
        const float* Qb = QKV + (size_t)(b * SEQ + q0 + wid * 16 + gid) * QKV_N + h * D_KV;
        #pragma unroll
        for (int k = 0; k < 8; k++) {
            qfu[k][0] = __float_as_uint(Qb[k * 8 + tig]);
            qfu[k][1] = __float_as_uint(Qb[8 * QKV_N + k * 8 + tig]);
            qfu[k][2] = __float_as_uint(Qb[k * 8 + tig + 4]);
            qfu[k][3] = __float_as_uint(Qb[8 * QKV_N + k * 8 + tig + 4]);
        }
    }

    auto load_kv = [&](int buf, int k0) {
        const float* Kg = QKV + INNER + h * D_KV;
        const float* Vg = QKV + 2 * INNER + h * D_KV;
        uint32_t kb = smb + (uint32_t)(buf * KBUF) * 4;
        uint32_t vb = smb + (uint32_t)(2 * KBUF + buf * VBUF) * 4;
        #pragma unroll
        for (int t = 0; t < 8; t++) {
            int idx = tid + t * 128;
            int row = idx >> 4;
            int c4 = (idx & 15) * 4;
            size_t gaddr = (size_t)(b * SEQ + k0 + row) * QKV_N + c4;
            CP_ASYNC16(kb + (uint32_t)(row * KPITCH + c4) * 4, Kg + gaddr);
            CP_ASYNC16(vb + (uint32_t)(row * VPITCH + c4) * 4, Vg + gaddr);
        }
    };

    float oacc[8][4];
    #pragma unroll
    for (int nj = 0; nj < 8; nj++)
        #pragma unroll
        for (int c = 0; c < 4; c++) oacc[nj][c] = 0.f;
    float m0 = -1e30f, m1 = -1e30f, l0 = 0.f, l1 = 0.f;

    load_kv(0, 0);
    CP_COMMIT();

    for (int it = 0; it < SEQ / 64; it++) {
        const int cur = it & 1;
        const int k0 = it * 64;
        cp_wait<0>();
        __syncthreads();
        if (it + 1 < SEQ / 64) {
            load_kv(cur ^ 1, k0 + 64);
            CP_COMMIT();
        }
        const uint32_t kbase = smb + (uint32_t)(cur * KBUF) * 4;
        const float* Vs = Vbp[cur];

        // S = Q @ K^T (ldmatrix B fragments)
        float sacc[8][4];
        #pragma unroll
        for (int nj = 0; nj < 8; nj++)
            #pragma unroll
            for (int c = 0; c < 4; c++) sacc[nj][c] = 0.f;
        #pragma unroll
        for (int ks = 0; ks < 8; ks++) {
            const uint32_t kso = (uint32_t)(ks * 8) * 4;
            uint32_t bb[4][4];
            #pragma unroll
            for (int p = 0; p < 4; p++)
                ldsm_x4(kbase + kboff + (uint32_t)(p * 16 * KPITCH) * 4 + kso, bb[p]);
            #pragma unroll
            for (int p = 0; p < 4; p++) {
                mma_tf32u(sacc[2 * p], qfu[ks], bb[p]);
                mma_tf32u(sacc[2 * p + 1], qfu[ks], bb[p] + 2);
            }
        }

        // bias + online softmax
        const float* bt = tab + h * TAB_LEN + 1023 + k0 - (q0 + wid * 16);
        float rx0 = -1e30f, rx1 = -1e30f;
        #pragma unroll
        for (int nj = 0; nj < 8; nj++) {
            int c = nj * 8 + 2 * tig;
            sacc[nj][0] += __ldg(bt + c - gid);
            sacc[nj][1] += __ldg(bt + c + 1 - gid);
            sacc[nj][2] += __ldg(bt + c - gid - 8);
            sacc[nj][3] += __ldg(bt + c + 1 - gid - 8);
            rx0 = fmaxf(rx0, fmaxf(sacc[nj][0], sacc[nj][1]));
            rx1 = fmaxf(rx1, fmaxf(sacc[nj][2], sacc[nj][3]));
        }
        rx0 = fmaxf(rx0, __shfl_xor_sync(0xFFFFFFFFu, rx0, 1));
        rx0 = fmaxf(rx0, __shfl_xor_sync(0xFFFFFFFFu, rx0, 2));
        rx1 = fmaxf(rx1, __shfl_xor_sync(0xFFFFFFFFu, rx1, 1));
        rx1 = fmaxf(rx1, __shfl_xor_sync(0xFFFFFFFFu, rx1, 2));
        float mn0 = fmaxf(m0, rx0), mn1 = fmaxf(m1, rx1);
        float sc0 = __expf(m0 - mn0), sc1 = __expf(m1 - mn1);
        m0 = mn0; m1 = mn1;

        float rs0 = 0.f, rs1 = 0.f;
        float* pw0 = Ps + (wid * 16 + gid) * PPITCH;
        float* pw1 = pw0 + 8 * PPITCH;
        #pragma unroll
        for (int nj = 0; nj < 8; nj++) {
            int c = nj * 8 + 2 * tig;
            float p0 = __expf(sacc[nj][0] - m0);
            float p1 = __expf(sacc[nj][1] - m0);
            float p2 = __expf(sacc[nj][2] - m1);
            float p3 = __expf(sacc[nj][3] - m1);
            rs0 += p0 + p1; rs1 += p2 + p3;
            *(float2*)(pw0 + c) = make_float2(to_tf32(p0), to_tf32(p1));
            *(float2*)(pw1 + c) = make_float2(to_tf32(p2), to_tf32(p3));
        }
        rs0 += __shfl_xor_sync(0xFFFFFFFFu, rs0, 1);
        rs0 += __shfl_xor_sync(0xFFFFFFFFu, rs0, 2);
        rs1 += __shfl_xor_sync(0xFFFFFFFFu, rs1, 1);
        rs1 += __shfl_xor_sync(0xFFFFFFFFu, rs1, 2);
        l0 = l0 * sc0 + rs0;
        l1 = l1 * sc1 + rs1;
        #pragma unroll
        for (int nj = 0; nj < 8; nj++) {
            oacc[nj][0] *= sc0; oacc[nj][1] *= sc0;
            oacc[nj][2] *= sc1; oacc[nj][3] *= sc1;
        }
        __syncwarp();

        // O += P @ V (ldmatrix A fragments; V scalar, conflict-free)
        #pragma unroll
        for (int k = 0; k < 8; k++) {
            uint32_t af[4];
            ldsm_x4(paoff + (uint32_t)(k * 8) * 4, af);
            #pragma unroll
            for (int nj = 0; nj < 8; nj++) {
                float bf[2];
                const float* vp = Vs + (k * 8 + tig) * VPITCH + nj * 8 + gid;
                bf[0] = vp[0];
                bf[1] = vp[4 * VPITCH];
                mma_tf32u(oacc[nj], af, (const uint32_t*)bf);
            }
        }
    }

    float i0 = 1.f / l0, i1 = 1.f / l1;
    float* ob = O + (size_t)(b * SEQ + q0 + wid * 16 + gid) * INNER + h * D_KV;
    #pragma unroll
    for (int nj = 0; nj < 8; nj++) {
        int c = nj * 8 + 2 * tig;
        *(float2*)(ob + c) = make_float2(to_tf32(oacc[nj][0] * i0),
                                         to_tf32(oacc[nj][1] * i0));
        *(float2*)(ob + 8 * INNER + c) = make_float2(to_tf32(oacc[nj][2] * i1),
                                                     to_tf32(oacc[nj][3] * i1));
    }
}

// ---------------- launch -----------------------------------------------------
extern "C" void kernel_launch(void* const* d_in, const int* in_sizes, int n_in,
                              void* d_out, int out_size) {
    const float* hidden  = (const float*)d_in[0];
    const float* ln1_w   = (const float*)d_in[1];
    const float* wq      = (const float*)d_in[2];
    const float* wk      = (const float*)d_in[3];
    const float* wv      = (const float*)d_in[4];
    const float* wo      = (const float*)d_in[5];
    const float* relbias = (const float*)d_in[6];
    const float* ln2_w   = (const float*)d_in[7];
    const float* wi      = (const float*)d_in[8];
    const float* wo_ff   = (const float*)d_in[9];
    float* out = (float*)d_out;

    float *px, *pqkv, *pctx, *ph, *py, *pmid, *pbias;
    float *pwqkv, *pwo, *pwi, *pwoff;
    cudaGetSymbolAddress((void**)&px,    g_x);
    cudaGetSymbolAddress((void**)&pqkv,  g_qkv);
    cudaGetSymbolAddress((void**)&pctx,  g_ctx);
    cudaGetSymbolAddress((void**)&ph,    g_h);
    cudaGetSymbolAddress((void**)&py,    g_y);
    cudaGetSymbolAddress((void**)&pmid,  g_mid);
    cudaGetSymbolAddress((void**)&pbias, g_bias);
    cudaGetSymbolAddress((void**)&pwqkv, g_wqkv_r);
    cudaGetSymbolAddress((void**)&pwo,   g_wo_r);
    cudaGetSymbolAddress((void**)&pwi,   g_wi_r);
    cudaGetSymbolAddress((void**)&pwoff, g_woff_r);

    cudaFuncSetAttribute(gemm_tf32_kernel<1>, cudaFuncAttributeMaxDynamicSharedMemorySize, GEMM_SMEM);
    cudaFuncSetAttribute(gemm_tf32_kernel<3>, cudaFuncAttributeMaxDynamicSharedMemorySize, GEMM_SMEM);
    cudaFuncSetAttribute(gemm_tf32_kernel<4>, cudaFuncAttributeMaxDynamicSharedMemorySize, GEMM_SMEM);
    cudaFuncSetAttribute(attention_mma_kernel, cudaFuncAttributeMaxDynamicSharedMemorySize, ATT_SMEM);

    // 0: fused weight rounding
    round_all_kernel<<<(N4TOT + 255) / 256, 256>>>(
        (const float4*)wq, (const float4*)wk, (const float4*)wv,
        (const float4*)wo, (const float4*)wi, (const float4*)wo_ff,
        (float4*)pwqkv, (float4*)pwo, (float4*)pwi, (float4*)pwoff);

    // 1,2
    bias_table_kernel<<<(TAB_LEN + 255) / 256, 256>>>(relbias, pbias);
    rmsnorm_kernel<<<M_ROWS, 256>>>(hidden, ln1_w, px);

    // 3: QKV projection (rounded output)
    gemm_tf32_kernel<4><<<dim3(QKV_N / 128, M_ROWS / 128), 256, GEMM_SMEM>>>(
        px, pwqkv, pqkv, M_ROWS, QKV_N, D_MODEL, D_MODEL);

    // 4: attention
    attention_mma_kernel<<<dim3(SEQ / 64, BATCH * N_HEADS), 128, ATT_SMEM>>>(
        pqkv, pbias, pctx);

    // 5 (ncu target): h = hidden + ctx @ wo^T (split-K2 atomic)
    cudaMemcpyAsync(ph, hidden, (size_t)M_ROWS * D_MODEL * sizeof(float),
                    cudaMemcpyDeviceToDevice);
    gemm_tf32_kernel<3><<<dim3(D_MODEL / 128, M_ROWS / 128, 2), 256, GEMM_SMEM>>>(
        pctx, pwo, ph, M_ROWS, D_MODEL, INNER, INNER / 2);

    // 6
    rmsnorm_kernel<<<M_ROWS, 256>>>(ph, ln2_w, py);

    // 7: mid = relu(y @ wi^T)
    gemm_tf32_kernel<1><<<dim3(D_FF / 128, M_ROWS / 128), 256, GEMM_SMEM>>>(
        py, pwi, pmid, M_ROWS, D_FF, D_MODEL, D_MODEL);

    // 8: out = h + mid @ wo_ff^T (split-K2 atomic)
    cudaMemcpyAsync(out, ph, (size_t)M_ROWS * D_MODEL * sizeof(float),
                    cudaMemcpyDeviceToDevice);
    gemm_tf32_kernel<3><<<dim3(D_MODEL / 128, M_ROWS / 128, 2), 256, GEMM_SMEM>>>(
        pmid, pwoff, out, M_ROWS, D_MODEL, D_FF, D_FF / 2);
}